// round 11
// baseline (speedup 1.0000x reference)
#include <cuda_runtime.h>
#include <cstdint>
#include <cstddef>

#define BB 4
#define TT 32
#define NN 1024
#define KK 16
#define HD 128

// d_out layout (float32, concatenated outputs):
//   out1: [B][T][132][N]      17,301,504
//   h:    [B][128][N]            524,288   @ 17,301,504
//   c:    [B][128][N]            524,288   @ 17,825,792
//   gidx: [B][T][N][K] (cast)  2,097,152   @ 18,350,080
#define OFF_H 17301504
#define OFF_C 17825792
#define OFF_I 18350080

#define SBT   (BB*NN*HD)           // per-timestep h/c slab: 524288 floats
#define VSLAB ((size_t)BB*NN*512)  // per-timestep V slab: 2M floats
#define NBLK  256                  // persistent grid size (co-resident: 2/SM x 148 SM >= 256)

// ---------------- device scratch (static, allowed) ----------------
__device__ float g_U[BB*NN*512];
__device__ float g_V0[(size_t)TT*VSLAB];      // V layer0, all t
__device__ float g_V1[(size_t)TT*VSLAB];      // V layer1, all t
__device__ float g_hs0[(size_t)TT*BB*NN*HD];  // [t][b][n][j]
__device__ float g_hs1[(size_t)TT*BB*NN*HD];
__device__ float g_c[2][BB*NN*HD];            // ping-pong, [b][n][j]
__device__ int   g_idx[BB*TT*NN*KK];
__device__ float g_Wd0[512*4];
__device__ float g_Wd1[512*4];

// ---------------- software grid barrier ----------------
__device__ unsigned g_bar_cnt = 0;
__device__ volatile unsigned g_bar_gen = 0;

__device__ __forceinline__ void grid_barrier() {
    __threadfence();          // flush this thread's global writes
    __syncthreads();
    if (threadIdx.x == 0) {
        unsigned gen = g_bar_gen;
        if (atomicAdd(&g_bar_cnt, 1) == (unsigned)(gridDim.x - 1)) {
            g_bar_cnt = 0;
            __threadfence();
            g_bar_gen = gen + 1;   // release
        } else {
            while (g_bar_gen == gen) __nanosleep(64);
        }
    }
    __syncthreads();
}

// ---------------- fast math helpers ----------------
__device__ __forceinline__ float sigf(float x) {
    return __fdividef(1.0f, 1.0f + __expf(-x));
}

// Combined-denominator gate activations (8 MUFU/elem):
//   sig(gi)*tanh(gg) = (1-b)/((1+a)(1+b)),  a=e^-gi, b=e^-2gg
__device__ __forceinline__ void gate4(
    float gi, float gf, float go, float gg, float cg,
    float& cn_out, float& hn_out)
{
    float ea = __expf(fminf(-gi, 80.f));
    float eb = __expf(fminf(-2.0f*gg, 80.f));
    float it = __fdividef(1.0f - eb, (1.0f + ea) * (1.0f + eb));
    float cn = fmaf(sigf(gf), cg, it);
    float ec = __expf(fminf(-go, 80.f));
    float ed = __expf(fminf(-2.0f*cn, 80.f));
    float hn = __fdividef(1.0f - ed, (1.0f + ec) * (1.0f + ed));
    cn_out = cn; hn_out = hn;
}

// ---------------- KNN: stable top-16 smallest d2 ----------------
// Rounding matches XLA's fp32 emission:
//   q2/r2: separate mul + add (NO fma contraction); qr: fma chain from 0;
//   d2: fl( fl(q2 + r2) - 2*qr )
__global__ __launch_bounds__(256) void knn_kernel(const float* __restrict__ x) {
    __shared__ float rx[NN], ry[NN], rz[NN], rr[NN];
    int t = blockIdx.y, b = blockIdx.z;
    int f = t ? t - 1 : 0;
    const float* rb = x + ((size_t)(b*TT + f) * 4) * NN;
    for (int i = threadIdx.x; i < NN; i += 256) {
        float a = rb[i], bb = rb[NN + i], cc = rb[2*NN + i];
        rx[i] = a; ry[i] = bb; rz[i] = cc;
        float s = __fadd_rn(__fmul_rn(a, a), __fmul_rn(bb, bb));
        rr[i] = __fadd_rn(s, __fmul_rn(cc, cc));
    }
    __syncthreads();

    int n = blockIdx.x * 256 + threadIdx.x;
    const float* qb = x + ((size_t)(b*TT + t) * 4) * NN;
    float qx = qb[n], qy = qb[NN + n], qz = qb[2*NN + n];
    float q2 = __fadd_rn(__fadd_rn(__fmul_rn(qx, qx), __fmul_rn(qy, qy)),
                         __fmul_rn(qz, qz));

    float bd[KK]; int bi[KK];
#pragma unroll
    for (int k = 0; k < KK; ++k) { bd[k] = 3.402823466e38f; bi[k] = 0; }

    for (int m = 0; m < NN; ++m) {
        float qr = __fmaf_rn(qz, rz[m],
                    __fmaf_rn(qy, ry[m],
                     __fmaf_rn(qx, rx[m], 0.0f)));
        float d  = __fsub_rn(__fadd_rn(q2, rr[m]), __fmul_rn(2.0f, qr));
        if (d < bd[KK-1]) {
            bd[KK-1] = d; bi[KK-1] = m;
#pragma unroll
            for (int jj = KK-1; jj > 0; --jj) {
                if (bd[jj] < bd[jj-1]) {
                    float td = bd[jj]; bd[jj] = bd[jj-1]; bd[jj-1] = td;
                    int   ti = bi[jj]; bi[jj] = bi[jj-1]; bi[jj-1] = ti;
                }
            }
        }
    }
    int* op = g_idx + (((size_t)b*TT + t) * NN + n) * KK;
#pragma unroll
    for (int k = 0; k < KK; ++k) op[k] = bi[k];
}

// ---------------- weight prep: Wd = Wx[:, :4] - Wpd ----------------
__global__ void wdiff_kernel(const float* __restrict__ w0, const float* __restrict__ w1) {
    int o = blockIdx.x * 128 + threadIdx.x;
    if (o < 512) {
#pragma unroll
        for (int c = 0; c < 4; ++c) {
            g_Wd0[o*4 + c] = w0[o*136 + c] - w0[o*136 + 4 + c];
            g_Wd1[o*4 + c] = w1[o*264 + c] - w1[o*264 + 132 + c];
        }
    }
}

// ===== shared GEMM tile body: 128o x 64m, 256 threads, 8o x 4m per thread ===
// acc order per output element: pos channels (c=0..3) then k ascending — the
// same chain as previous rounds => bitwise-identical results.
struct TileSmem {
    float sWp[4][128];
    float sP [4][64];
    float sW [16][132];
    float sIn[16][68];
};

// ---------------- batched V GEMM (independent of recurrence) ----------------
// mode 0: V0 = Wd0*pos + b0 (pos only);  mode 1: V1 = Wd1*pos + Wh*hs0(t) + b1
__global__ __launch_bounds__(256, 2) void vgemm_kernel(
    int mode,
    const float* __restrict__ x,
    const float* __restrict__ b0,
    const float* __restrict__ w1, const float* __restrict__ b1)
{
    int b = blockIdx.z & 3, tt = blockIdx.z >> 2;

    const float* Wp   = mode ? g_Wd1 : g_Wd0;
    const float* bias = mode ? b1 : b0;
    const float* Wh   = mode ? (w1 + 4) : nullptr;
    const int    ldh  = 264;
    const float* H    = mode ? (g_hs0 + (size_t)tt * SBT) : nullptr;
    float* Out        = (mode ? g_V1 : g_V0) + (size_t)tt * VSLAB;

    __shared__ TileSmem s;

    int tid = threadIdx.x;
    int o0  = blockIdx.x * 128;
    int m0  = blockIdx.y * 64;
    int of  = (tid & 15) * 8;   // 8 outputs per thread
    int mf  = (tid >> 4) * 4;   // 4 points per thread

    const float* Pb = x + ((size_t)(b*TT + tt) * 4) * NN + m0;
    for (int i = tid; i < 512; i += 256) {
        int c = i >> 7, oo = i & 127;
        s.sWp[c][oo] = Wp[(size_t)(o0 + oo) * 4 + c];
    }
    {
        int c = tid >> 6, mm = tid & 63;
        s.sP[c][mm] = Pb[(size_t)c * NN + mm];
    }
    __syncthreads();

    float acc[4][8];
#pragma unroll
    for (int oi = 0; oi < 8; ++oi) {
        float bv = bias[o0 + of + oi];
#pragma unroll
        for (int mi = 0; mi < 4; ++mi) acc[mi][oi] = bv;
    }

#pragma unroll
    for (int c = 0; c < 4; ++c) {
        float a[8];
#pragma unroll
        for (int oi = 0; oi < 8; ++oi) a[oi] = s.sWp[c][of + oi];
#pragma unroll
        for (int mi = 0; mi < 4; ++mi) {
            float p = s.sP[c][mf + mi];
#pragma unroll
            for (int oi = 0; oi < 8; ++oi)
                acc[mi][oi] = fmaf(a[oi], p, acc[mi][oi]);
        }
    }

    if (Wh && H) {
        const float* Hb = H + ((size_t)b * NN + m0) * HD;
        for (int k0 = 0; k0 < HD; k0 += 16) {
            for (int q = tid; q < 512; q += 256) {   // W tile: 128 o x 16 k
                int row = q >> 2, kq = (q & 3) * 4;
                float4 wv = *reinterpret_cast<const float4*>(
                    Wh + (size_t)(o0 + row) * ldh + k0 + kq);
                s.sW[kq  ][row] = wv.x; s.sW[kq+1][row] = wv.y;
                s.sW[kq+2][row] = wv.z; s.sW[kq+3][row] = wv.w;
            }
            {   // In tile: 16 k x 64 m
                int mm = tid >> 2, kq = (tid & 3) * 4;
                float4 hv = *reinterpret_cast<const float4*>(
                    Hb + (size_t)mm * HD + k0 + kq);
                s.sIn[kq  ][mm] = hv.x; s.sIn[kq+1][mm] = hv.y;
                s.sIn[kq+2][mm] = hv.z; s.sIn[kq+3][mm] = hv.w;
            }
            __syncthreads();
#pragma unroll
            for (int k = 0; k < 16; ++k) {
                float4 a0 = *reinterpret_cast<const float4*>(&s.sW[k][of]);
                float4 a1 = *reinterpret_cast<const float4*>(&s.sW[k][of + 4]);
                float aa[8] = {a0.x,a0.y,a0.z,a0.w,a1.x,a1.y,a1.z,a1.w};
                float4 p = *reinterpret_cast<const float4*>(&s.sIn[k][mf]);
                float pb[4] = {p.x, p.y, p.z, p.w};
#pragma unroll
                for (int mi = 0; mi < 4; ++mi)
#pragma unroll
                    for (int oi = 0; oi < 8; ++oi)
                        acc[mi][oi] = fmaf(aa[oi], pb[mi], acc[mi][oi]);
            }
            __syncthreads();
        }
    }

    float* Ob = Out + ((size_t)b * NN + m0 + mf) * 512 + o0 + of;
#pragma unroll
    for (int mi = 0; mi < 4; ++mi) {
        *reinterpret_cast<float4*>(Ob + (size_t)mi * 512) =
            make_float4(acc[mi][0], acc[mi][1], acc[mi][2], acc[mi][3]);
        *reinterpret_cast<float4*>(Ob + (size_t)mi * 512 + 4) =
            make_float4(acc[mi][4], acc[mi][5], acc[mi][6], acc[mi][7]);
    }
}

// ---------------- persistent per-layer kernel: full 32-step recurrence ------
// Phase A: U = Wp*pos + Wh*h_prev   (256 tiles of 128o x 64m, 1 per block)
// Phase B: gate + max-over-K        (4096 points, 1 warp each)
// Cross-step / cross-block mutable data read via __ldcg (L2-coherent).
__global__ __launch_bounds__(256, 2) void layer_kernel(
    int layer, const float* __restrict__ x,
    const float* __restrict__ w0, const float* __restrict__ w1)
{
    const float* Wp = layer ? (w1 + 132) : (w0 + 4);
    const float* Wh = layer ? (w1 + 136) : (w0 + 8);
    const int    ldw = layer ? 264 : 136;
    const float* Vbase = layer ? g_V1 : g_V0;
    float*       Hs    = layer ? g_hs1 : g_hs0;

    __shared__ TileSmem s;

    int tid  = threadIdx.x;
    int warp = tid >> 5, lane = tid & 31;

    // fixed tile assignment: 4 o-tiles x 16 m-tiles x 4 b = 256 = NBLK
    int o0 = (blockIdx.x & 3) * 128;
    int m0 = ((blockIdx.x >> 2) & 15) * 64;
    int bA = blockIdx.x >> 6;
    int of = (tid & 15) * 8;
    int mf = (tid >> 4) * 4;

    for (int t = 0; t < TT; ++t) {
        int frame = t ? t - 1 : 0;
        const float* Hprev = t ? (Hs + (size_t)(t-1) * SBT) : nullptr;

        // ---------------- Phase A: U ----------------
        {
            const float* Pb = x + ((size_t)(bA*TT + frame) * 4) * NN + m0;
            for (int i = tid; i < 512; i += 256) {
                int c = i >> 7, oo = i & 127;
                s.sWp[c][oo] = Wp[(size_t)(o0 + oo) * ldw + c];
            }
            {
                int c = tid >> 6, mm = tid & 63;
                s.sP[c][mm] = Pb[(size_t)c * NN + mm];
            }
            __syncthreads();

            float acc[4][8];
#pragma unroll
            for (int mi = 0; mi < 4; ++mi)
#pragma unroll
                for (int oi = 0; oi < 8; ++oi) acc[mi][oi] = 0.f;

#pragma unroll
            for (int c = 0; c < 4; ++c) {
                float a[8];
#pragma unroll
                for (int oi = 0; oi < 8; ++oi) a[oi] = s.sWp[c][of + oi];
#pragma unroll
                for (int mi = 0; mi < 4; ++mi) {
                    float p = s.sP[c][mf + mi];
#pragma unroll
                    for (int oi = 0; oi < 8; ++oi)
                        acc[mi][oi] = fmaf(a[oi], p, acc[mi][oi]);
                }
            }

            if (Hprev) {
                const float* Hb = Hprev + ((size_t)bA * NN + m0) * HD;
                for (int k0 = 0; k0 < HD; k0 += 16) {
                    for (int q = tid; q < 512; q += 256) {   // W: 128 o x 16 k
                        int row = q >> 2, kq = (q & 3) * 4;
                        float4 wv = *reinterpret_cast<const float4*>(
                            Wh + (size_t)(o0 + row) * ldw + k0 + kq);
                        s.sW[kq  ][row] = wv.x; s.sW[kq+1][row] = wv.y;
                        s.sW[kq+2][row] = wv.z; s.sW[kq+3][row] = wv.w;
                    }
                    {   // h (written by other blocks last step) -> L2-coherent
                        int mm = tid >> 2, kq = (tid & 3) * 4;
                        float4 hv = __ldcg(reinterpret_cast<const float4*>(
                            Hb + (size_t)mm * HD + k0 + kq));
                        s.sIn[kq  ][mm] = hv.x; s.sIn[kq+1][mm] = hv.y;
                        s.sIn[kq+2][mm] = hv.z; s.sIn[kq+3][mm] = hv.w;
                    }
                    __syncthreads();
#pragma unroll
                    for (int k = 0; k < 16; ++k) {
                        float4 a0 = *reinterpret_cast<const float4*>(&s.sW[k][of]);
                        float4 a1 = *reinterpret_cast<const float4*>(&s.sW[k][of + 4]);
                        float aa[8] = {a0.x,a0.y,a0.z,a0.w,a1.x,a1.y,a1.z,a1.w};
                        float4 p = *reinterpret_cast<const float4*>(&s.sIn[k][mf]);
                        float pb[4] = {p.x, p.y, p.z, p.w};
#pragma unroll
                        for (int mi = 0; mi < 4; ++mi)
#pragma unroll
                            for (int oi = 0; oi < 8; ++oi)
                                acc[mi][oi] = fmaf(aa[oi], pb[mi], acc[mi][oi]);
                    }
                    __syncthreads();
                }
            }

            float* Ob = g_U + ((size_t)bA * NN + m0 + mf) * 512 + o0 + of;
#pragma unroll
            for (int mi = 0; mi < 4; ++mi) {
                *reinterpret_cast<float4*>(Ob + (size_t)mi * 512) =
                    make_float4(acc[mi][0], acc[mi][1], acc[mi][2], acc[mi][3]);
                *reinterpret_cast<float4*>(Ob + (size_t)mi * 512 + 4) =
                    make_float4(acc[mi][4], acc[mi][5], acc[mi][6], acc[mi][7]);
            }
        }

        grid_barrier();

        // ---------------- Phase B: gate + max over K ----------------
        {
            const float* Vt    = Vbase + (size_t)t * VSLAB;
            const float* Cprev = t ? g_c[(t-1) & 1] : nullptr;
            float* Hout = Hs + (size_t)t * SBT;
            float* Cout = g_c[t & 1];

            for (int p = blockIdx.x * 8 + warp; p < BB*NN; p += NBLK * 8) {
                int b = p >> 10, n = p & 1023;
                int mreg = 0;
                if (lane < KK)
                    mreg = g_idx[(((size_t)b*TT + t) * NN + n) * KK + lane];

                const float* Vp = Vt + ((size_t)b * NN + n) * 512 + lane * 4;
                float4 v0 = *reinterpret_cast<const float4*>(Vp);
                float4 v1 = *reinterpret_cast<const float4*>(Vp + 128);
                float4 v2 = *reinterpret_cast<const float4*>(Vp + 256);
                float4 v3 = *reinterpret_cast<const float4*>(Vp + 384);

                float4 hmax = make_float4(-1e30f,-1e30f,-1e30f,-1e30f);
                float4 cmax = hmax;
#pragma unroll 4
                for (int k = 0; k < KK; ++k) {
                    int m = __shfl_sync(0xffffffffu, mreg, k);
                    const float* Up = g_U + ((size_t)b * NN + m) * 512 + lane * 4;
                    float4 u0 = __ldcg(reinterpret_cast<const float4*>(Up));
                    float4 u1 = __ldcg(reinterpret_cast<const float4*>(Up + 128));
                    float4 u2 = __ldcg(reinterpret_cast<const float4*>(Up + 256));
                    float4 u3 = __ldcg(reinterpret_cast<const float4*>(Up + 384));
                    float4 cg = make_float4(0.f, 0.f, 0.f, 0.f);
                    if (Cprev)
                        cg = __ldcg(reinterpret_cast<const float4*>(
                                 Cprev + ((size_t)b * NN + m) * HD + lane * 4));
                    float cn, hn;
                    gate4(v0.x+u0.x, v1.x+u1.x, v2.x+u2.x, v3.x+u3.x, cg.x, cn, hn);
                    cmax.x = fmaxf(cmax.x, cn); hmax.x = fmaxf(hmax.x, hn);
                    gate4(v0.y+u0.y, v1.y+u1.y, v2.y+u2.y, v3.y+u3.y, cg.y, cn, hn);
                    cmax.y = fmaxf(cmax.y, cn); hmax.y = fmaxf(hmax.y, hn);
                    gate4(v0.z+u0.z, v1.z+u1.z, v2.z+u2.z, v3.z+u3.z, cg.z, cn, hn);
                    cmax.z = fmaxf(cmax.z, cn); hmax.z = fmaxf(hmax.z, hn);
                    gate4(v0.w+u0.w, v1.w+u1.w, v2.w+u2.w, v3.w+u3.w, cg.w, cn, hn);
                    cmax.w = fmaxf(cmax.w, cn); hmax.w = fmaxf(hmax.w, hn);
                }
                size_t o = ((size_t)b * NN + n) * HD + lane * 4;
                *reinterpret_cast<float4*>(Hout + o) = hmax;
                *reinterpret_cast<float4*>(Cout + o) = cmax;
            }
        }

        grid_barrier();
    }
}

// ---------------- output assembly ----------------
__global__ void out1_pos_kernel(const float* __restrict__ x, float* __restrict__ out) {
    int i = blockIdx.x * 256 + threadIdx.x;  // B*T*4*N = 524288
    if (i < BB*TT*4*NN) {
        int bt = i >> 12;
        int r  = i & 4095;
        out[(size_t)bt * 132 * NN + r] = x[i];
    }
}

__global__ void out1_hs_kernel(float* __restrict__ out) {
    __shared__ float tile[32][33];
    int n0 = blockIdx.x * 32, j0 = blockIdx.y * 32, bt = blockIdx.z;
    int b = bt >> 5, t = bt & 31;
    int tx = threadIdx.x, ty = threadIdx.y;
    tile[ty][tx] = g_hs1[(((size_t)t*BB + b) * NN + n0 + ty) * HD + j0 + tx];
    __syncthreads();
    out[((size_t)bt * 132 + 4 + j0 + ty) * NN + n0 + tx] = tile[tx][ty];
}

__global__ void hc_kernel(float* __restrict__ out) {
    __shared__ float th[32][33];
    __shared__ float tc[32][33];
    int n0 = blockIdx.x * 32, j0 = blockIdx.y * 32, b = blockIdx.z;
    int tx = threadIdx.x, ty = threadIdx.y;
    th[ty][tx] = g_hs1[(((size_t)(TT-1)*BB + b) * NN + n0 + ty) * HD + j0 + tx];
    tc[ty][tx] = g_c[(TT-1) & 1][((size_t)b * NN + n0 + ty) * HD + j0 + tx];
    __syncthreads();
    size_t dst = ((size_t)b * HD + j0 + ty) * NN + n0 + tx;
    out[OFF_H + dst] = th[tx][ty];
    out[OFF_C + dst] = tc[tx][ty];
}

__global__ void idxf_kernel(float* __restrict__ out) {
    int i = blockIdx.x * 256 + threadIdx.x;  // 2,097,152
    out[OFF_I + i] = (float)g_idx[i];
}

// ---------------- launch ----------------
extern "C" void kernel_launch(void* const* d_in, const int* in_sizes, int n_in,
                              void* d_out, int out_size) {
    const float* x  = (const float*)d_in[0];
    const float* w0 = (const float*)d_in[1];
    const float* b0 = (const float*)d_in[2];
    const float* w1 = (const float*)d_in[3];
    const float* b1 = (const float*)d_in[4];
    float* out = (float*)d_out;

    knn_kernel<<<dim3(4, TT, BB), 256>>>(x);
    wdiff_kernel<<<4, 128>>>(w0, w1);

    dim3 gv(4, 16, BB*TT);   // batched V gemm: 128o x 64m tiles, 8192 blocks

    vgemm_kernel<<<gv, 256>>>(0, x, b0, w1, b1);   // V0, all t (pos only)
    layer_kernel<<<NBLK, 256>>>(0, x, w0, w1);     // layer 0: full recurrence
    vgemm_kernel<<<gv, 256>>>(1, x, b0, w1, b1);   // V1, all t (needs hs0)
    layer_kernel<<<NBLK, 256>>>(1, x, w0, w1);     // layer 1: full recurrence

    out1_pos_kernel<<<2048, 256>>>(x, out);
    out1_hs_kernel<<<dim3(32, 4, BB*TT), dim3(32, 32)>>>(out);
    hc_kernel<<<dim3(32, 4, BB), dim3(32, 32)>>>(out);
    idxf_kernel<<<8192, 256>>>(out);
}

// round 12
// speedup vs baseline: 1.2257x; 1.2257x over previous
#include <cuda_runtime.h>
#include <cstdint>
#include <cstddef>

#define BB 4
#define TT 32
#define NN 1024
#define KK 16
#define HD 128

// d_out layout (float32, concatenated outputs):
//   out1: [B][T][132][N]      17,301,504
//   h:    [B][128][N]            524,288   @ 17,301,504
//   c:    [B][128][N]            524,288   @ 17,825,792
//   gidx: [B][T][N][K] (cast)  2,097,152   @ 18,350,080
#define OFF_H 17301504
#define OFF_C 17825792
#define OFF_I 18350080

#define SBT   (BB*NN*HD)           // per-timestep h/c slab: 524288 floats
#define VSLAB ((size_t)BB*NN*512)  // per-timestep V slab: 2M floats
#define LBLK  128                  // persistent grid: 1 block/SM, 512 threads

// ---------------- device scratch (static, allowed) ----------------
__device__ float g_U[BB*NN*512];
__device__ float g_V0[(size_t)TT*VSLAB];      // V layer0, all t
__device__ float g_V1[(size_t)TT*VSLAB];      // V layer1, all t
__device__ float g_hs0[(size_t)TT*BB*NN*HD];  // [t][b][n][j]
__device__ float g_hs1[(size_t)TT*BB*NN*HD];
__device__ float g_c[2][BB*NN*HD];            // ping-pong, [b][n][j]
__device__ int   g_idx[BB*TT*NN*KK];
__device__ float g_Wd0[512*4];
__device__ float g_Wd1[512*4];

// ---------------- software grid barrier ----------------
__device__ unsigned g_bar_cnt = 0;
__device__ volatile unsigned g_bar_gen = 0;

__device__ __forceinline__ void grid_barrier() {
    __threadfence();          // flush this thread's global writes
    __syncthreads();
    if (threadIdx.x == 0) {
        unsigned gen = g_bar_gen;
        if (atomicAdd(&g_bar_cnt, 1) == (unsigned)(gridDim.x - 1)) {
            g_bar_cnt = 0;
            __threadfence();
            g_bar_gen = gen + 1;   // release
        } else {
            while (g_bar_gen == gen) __nanosleep(64);
        }
    }
    __syncthreads();
}

// ---------------- fast math helpers ----------------
__device__ __forceinline__ float sigf(float x) {
    return __fdividef(1.0f, 1.0f + __expf(-x));
}

// Combined-denominator gate activations (8 MUFU/elem):
//   sig(gi)*tanh(gg) = (1-b)/((1+a)(1+b)),  a=e^-gi, b=e^-2gg
__device__ __forceinline__ void gate4(
    float gi, float gf, float go, float gg, float cg,
    float& cn_out, float& hn_out)
{
    float ea = __expf(fminf(-gi, 80.f));
    float eb = __expf(fminf(-2.0f*gg, 80.f));
    float it = __fdividef(1.0f - eb, (1.0f + ea) * (1.0f + eb));
    float cn = fmaf(sigf(gf), cg, it);
    float ec = __expf(fminf(-go, 80.f));
    float ed = __expf(fminf(-2.0f*cn, 80.f));
    float hn = __fdividef(1.0f - ed, (1.0f + ec) * (1.0f + ed));
    cn_out = cn; hn_out = hn;
}

// ---------------- KNN: stable top-16 smallest d2 ----------------
// Rounding matches XLA's fp32 emission:
//   q2/r2: separate mul + add (NO fma contraction); qr: fma chain from 0;
//   d2: fl( fl(q2 + r2) - 2*qr )
__global__ __launch_bounds__(256) void knn_kernel(const float* __restrict__ x) {
    __shared__ float rx[NN], ry[NN], rz[NN], rr[NN];
    int t = blockIdx.y, b = blockIdx.z;
    int f = t ? t - 1 : 0;
    const float* rb = x + ((size_t)(b*TT + f) * 4) * NN;
    for (int i = threadIdx.x; i < NN; i += 256) {
        float a = rb[i], bb = rb[NN + i], cc = rb[2*NN + i];
        rx[i] = a; ry[i] = bb; rz[i] = cc;
        float s = __fadd_rn(__fmul_rn(a, a), __fmul_rn(bb, bb));
        rr[i] = __fadd_rn(s, __fmul_rn(cc, cc));
    }
    __syncthreads();

    int n = blockIdx.x * 256 + threadIdx.x;
    const float* qb = x + ((size_t)(b*TT + t) * 4) * NN;
    float qx = qb[n], qy = qb[NN + n], qz = qb[2*NN + n];
    float q2 = __fadd_rn(__fadd_rn(__fmul_rn(qx, qx), __fmul_rn(qy, qy)),
                         __fmul_rn(qz, qz));

    float bd[KK]; int bi[KK];
#pragma unroll
    for (int k = 0; k < KK; ++k) { bd[k] = 3.402823466e38f; bi[k] = 0; }

    for (int m = 0; m < NN; ++m) {
        float qr = __fmaf_rn(qz, rz[m],
                    __fmaf_rn(qy, ry[m],
                     __fmaf_rn(qx, rx[m], 0.0f)));
        float d  = __fsub_rn(__fadd_rn(q2, rr[m]), __fmul_rn(2.0f, qr));
        if (d < bd[KK-1]) {
            bd[KK-1] = d; bi[KK-1] = m;
#pragma unroll
            for (int jj = KK-1; jj > 0; --jj) {
                if (bd[jj] < bd[jj-1]) {
                    float td = bd[jj]; bd[jj] = bd[jj-1]; bd[jj-1] = td;
                    int   ti = bi[jj]; bi[jj] = bi[jj-1]; bi[jj-1] = ti;
                }
            }
        }
    }
    int* op = g_idx + (((size_t)b*TT + t) * NN + n) * KK;
#pragma unroll
    for (int k = 0; k < KK; ++k) op[k] = bi[k];
}

// ---------------- weight prep: Wd = Wx[:, :4] - Wpd ----------------
__global__ void wdiff_kernel(const float* __restrict__ w0, const float* __restrict__ w1) {
    int o = blockIdx.x * 128 + threadIdx.x;
    if (o < 512) {
#pragma unroll
        for (int c = 0; c < 4; ++c) {
            g_Wd0[o*4 + c] = w0[o*136 + c] - w0[o*136 + 4 + c];
            g_Wd1[o*4 + c] = w1[o*264 + c] - w1[o*264 + 132 + c];
        }
    }
}

// ---------------- batched V GEMM (R10 form, known good) ----------------
// mode 0: V0 = Wd0*pos + b0 (pos only);  mode 1: V1 = Wd1*pos + Wh*hs0(t) + b1
// Tile 64o x 64m, 256 threads, thread = 4o x 4m.
__global__ __launch_bounds__(256) void vgemm_kernel(
    int mode,
    const float* __restrict__ x,
    const float* __restrict__ b0,
    const float* __restrict__ w1, const float* __restrict__ b1)
{
    int b = blockIdx.z & 3, tt = blockIdx.z >> 2;

    const float* Wp   = mode ? g_Wd1 : g_Wd0;
    const float* bias = mode ? b1 : b0;
    const float* Wh   = mode ? (w1 + 4) : nullptr;
    const int    ldh  = 264;
    const float* H    = mode ? (g_hs0 + (size_t)tt * SBT) : nullptr;
    float* Out        = (mode ? g_V1 : g_V0) + (size_t)tt * VSLAB;

    __shared__ float sWp[4][64];
    __shared__ float sP [4][64];
    __shared__ float sW [16][68];
    __shared__ float sIn[16][68];

    int tid = threadIdx.x;
    int o0  = blockIdx.x * 64;
    int m0  = blockIdx.y * 64;
    int of  = (tid & 15) * 4;
    int mf  = (tid >> 4) * 4;

    const float* Pb = x + ((size_t)(b*TT + tt) * 4) * NN + m0;
    {
        int c = tid >> 6, mm = tid & 63;
        sP[c][mm]  = Pb[(size_t)c * NN + mm];
        sWp[c][mm] = Wp[(size_t)(o0 + mm) * 4 + c];
    }
    __syncthreads();

    float acc[4][4];
    {
        float bv0 = bias[o0+of], bv1 = bias[o0+of+1], bv2 = bias[o0+of+2], bv3 = bias[o0+of+3];
#pragma unroll
        for (int mi = 0; mi < 4; ++mi) { acc[mi][0]=bv0; acc[mi][1]=bv1; acc[mi][2]=bv2; acc[mi][3]=bv3; }
    }

#pragma unroll
    for (int c = 0; c < 4; ++c) {
        float a0 = sWp[c][of], a1 = sWp[c][of+1], a2 = sWp[c][of+2], a3 = sWp[c][of+3];
#pragma unroll
        for (int mi = 0; mi < 4; ++mi) {
            float p = sP[c][mf + mi];
            acc[mi][0] = fmaf(a0, p, acc[mi][0]);
            acc[mi][1] = fmaf(a1, p, acc[mi][1]);
            acc[mi][2] = fmaf(a2, p, acc[mi][2]);
            acc[mi][3] = fmaf(a3, p, acc[mi][3]);
        }
    }

    if (Wh && H) {
        const float* Hb = H + ((size_t)b * NN + m0) * HD;
        int rr4 = tid >> 2;
        int k4  = (tid & 3) * 4;
        for (int k0 = 0; k0 < HD; k0 += 16) {
            {
                float4 wv = *reinterpret_cast<const float4*>(Wh + (size_t)(o0 + rr4) * ldh + k0 + k4);
                sW[k4  ][rr4] = wv.x; sW[k4+1][rr4] = wv.y;
                sW[k4+2][rr4] = wv.z; sW[k4+3][rr4] = wv.w;
            }
            {
                float4 hv = *reinterpret_cast<const float4*>(Hb + (size_t)rr4 * HD + k0 + k4);
                sIn[k4  ][rr4] = hv.x; sIn[k4+1][rr4] = hv.y;
                sIn[k4+2][rr4] = hv.z; sIn[k4+3][rr4] = hv.w;
            }
            __syncthreads();
#pragma unroll
            for (int k = 0; k < 16; ++k) {
                float4 a = *reinterpret_cast<const float4*>(&sW[k][of]);
                float4 p = *reinterpret_cast<const float4*>(&sIn[k][mf]);
                float pb[4] = {p.x, p.y, p.z, p.w};
#pragma unroll
                for (int mi = 0; mi < 4; ++mi) {
                    acc[mi][0] = fmaf(a.x, pb[mi], acc[mi][0]);
                    acc[mi][1] = fmaf(a.y, pb[mi], acc[mi][1]);
                    acc[mi][2] = fmaf(a.z, pb[mi], acc[mi][2]);
                    acc[mi][3] = fmaf(a.w, pb[mi], acc[mi][3]);
                }
            }
            __syncthreads();
        }
    }

    float* Ob = Out + ((size_t)b * NN + m0 + mf) * 512 + o0 + of;
#pragma unroll
    for (int mi = 0; mi < 4; ++mi) {
        float4 v = make_float4(acc[mi][0], acc[mi][1], acc[mi][2], acc[mi][3]);
        *reinterpret_cast<float4*>(Ob + (size_t)mi * 512) = v;
    }
}

// ---------------- persistent per-layer kernel: full 32-step recurrence ------
// Grid 128 x 512 threads: exactly 1 block/SM -> uniform barrier arrival.
// Phase A: U = Wp*pos + Wh*h_prev. 128 tiles of 128o x 128m, 1 per block.
//   Thread = 8o x 4m with SPLIT o-columns (of and of+64): all LDS.128
//   lane strides are 16B -> conflict-free. K-chunk = 32.
// Phase B: gate + max-over-K, 2048 warps, exactly 2 points each.
// Per-element accumulation order identical to prior rounds (bitwise same).
__global__ __launch_bounds__(512, 1) void layer_kernel(
    int layer, const float* __restrict__ x,
    const float* __restrict__ w0, const float* __restrict__ w1)
{
    const float* Wp = layer ? (w1 + 132) : (w0 + 4);
    const float* Wh = layer ? (w1 + 136) : (w0 + 8);
    const int    ldw = layer ? 264 : 136;
    const float* Vbase = layer ? g_V1 : g_V0;
    float*       Hs    = layer ? g_hs1 : g_hs0;

    __shared__ float sWp[4][128];
    __shared__ float sP [4][128];
    __shared__ float sW [32][132];
    __shared__ float sIn[32][132];

    int tid  = threadIdx.x;
    int warp = tid >> 5, lane = tid & 31;

    // tile assignment: 4 o-tiles x 8 m-tiles x 4 b = 128 = gridDim
    int o0 = (blockIdx.x & 3) * 128;
    int m0 = ((blockIdx.x >> 2) & 7) * 128;
    int bA = blockIdx.x >> 5;
    int of = (tid & 15) * 4;     // columns of..of+3 and of+64..of+67
    int mf = (tid >> 4) * 4;     // 4 points

    for (int t = 0; t < TT; ++t) {
        int frame = t ? t - 1 : 0;
        const float* Hprev = t ? (Hs + (size_t)(t-1) * SBT) : nullptr;

        // ---------------- Phase A: U ----------------
        {
            const float* Pb = x + ((size_t)(bA*TT + frame) * 4) * NN + m0;
            {
                int c = tid >> 7, mm = tid & 127;
                sWp[c][mm] = Wp[(size_t)(o0 + mm) * ldw + c];
                sP[c][mm]  = Pb[(size_t)c * NN + mm];
            }
            __syncthreads();

            float acc[4][8];
#pragma unroll
            for (int mi = 0; mi < 4; ++mi)
#pragma unroll
                for (int oi = 0; oi < 8; ++oi) acc[mi][oi] = 0.f;

#pragma unroll
            for (int c = 0; c < 4; ++c) {
                float a[8];
#pragma unroll
                for (int oi = 0; oi < 4; ++oi) {
                    a[oi]   = sWp[c][of + oi];
                    a[oi+4] = sWp[c][64 + of + oi];
                }
#pragma unroll
                for (int mi = 0; mi < 4; ++mi) {
                    float p = sP[c][mf + mi];
#pragma unroll
                    for (int oi = 0; oi < 8; ++oi)
                        acc[mi][oi] = fmaf(a[oi], p, acc[mi][oi]);
                }
            }

            if (Hprev) {
                const float* Hb = Hprev + ((size_t)bA * NN + m0) * HD;
                for (int k0 = 0; k0 < HD; k0 += 32) {
#pragma unroll
                    for (int rep = 0; rep < 2; ++rep) {   // 1024 float4 / 512 thr
                        int i = tid + rep * 512;
                        int row = i >> 3, kq = (i & 7) * 4;
                        float4 wv = *reinterpret_cast<const float4*>(
                            Wh + (size_t)(o0 + row) * ldw + k0 + kq);
                        sW[kq  ][row] = wv.x; sW[kq+1][row] = wv.y;
                        sW[kq+2][row] = wv.z; sW[kq+3][row] = wv.w;
                        // h written by other blocks last step -> L2-coherent
                        float4 hv = __ldcg(reinterpret_cast<const float4*>(
                            Hb + (size_t)row * HD + k0 + kq));
                        sIn[kq  ][row] = hv.x; sIn[kq+1][row] = hv.y;
                        sIn[kq+2][row] = hv.z; sIn[kq+3][row] = hv.w;
                    }
                    __syncthreads();
#pragma unroll
                    for (int k = 0; k < 32; ++k) {
                        float4 a0 = *reinterpret_cast<const float4*>(&sW[k][of]);
                        float4 a1 = *reinterpret_cast<const float4*>(&sW[k][64 + of]);
                        float aa[8] = {a0.x,a0.y,a0.z,a0.w,a1.x,a1.y,a1.z,a1.w};
                        float4 p = *reinterpret_cast<const float4*>(&sIn[k][mf]);
                        float pb[4] = {p.x, p.y, p.z, p.w};
#pragma unroll
                        for (int mi = 0; mi < 4; ++mi)
#pragma unroll
                            for (int oi = 0; oi < 8; ++oi)
                                acc[mi][oi] = fmaf(aa[oi], pb[mi], acc[mi][oi]);
                    }
                    __syncthreads();
                }
            }

            float* Ob = g_U + ((size_t)bA * NN + m0 + mf) * 512 + o0 + of;
#pragma unroll
            for (int mi = 0; mi < 4; ++mi) {
                *reinterpret_cast<float4*>(Ob + (size_t)mi * 512) =
                    make_float4(acc[mi][0], acc[mi][1], acc[mi][2], acc[mi][3]);
                *reinterpret_cast<float4*>(Ob + (size_t)mi * 512 + 64) =
                    make_float4(acc[mi][4], acc[mi][5], acc[mi][6], acc[mi][7]);
            }
        }

        grid_barrier();

        // ---------------- Phase B: gate + max over K ----------------
        {
            const float* Vt    = Vbase + (size_t)t * VSLAB;
            const float* Cprev = t ? g_c[(t-1) & 1] : nullptr;
            float* Hout = Hs + (size_t)t * SBT;
            float* Cout = g_c[t & 1];

            for (int p = blockIdx.x * 16 + warp; p < BB*NN; p += LBLK * 16) {
                int b = p >> 10, n = p & 1023;
                int mreg = 0;
                if (lane < KK)
                    mreg = g_idx[(((size_t)b*TT + t) * NN + n) * KK + lane];

                const float* Vp = Vt + ((size_t)b * NN + n) * 512 + lane * 4;
                float4 v0 = *reinterpret_cast<const float4*>(Vp);
                float4 v1 = *reinterpret_cast<const float4*>(Vp + 128);
                float4 v2 = *reinterpret_cast<const float4*>(Vp + 256);
                float4 v3 = *reinterpret_cast<const float4*>(Vp + 384);

                float4 hmax = make_float4(-1e30f,-1e30f,-1e30f,-1e30f);
                float4 cmax = hmax;
#pragma unroll 4
                for (int k = 0; k < KK; ++k) {
                    int m = __shfl_sync(0xffffffffu, mreg, k);
                    const float* Up = g_U + ((size_t)b * NN + m) * 512 + lane * 4;
                    float4 u0 = __ldcg(reinterpret_cast<const float4*>(Up));
                    float4 u1 = __ldcg(reinterpret_cast<const float4*>(Up + 128));
                    float4 u2 = __ldcg(reinterpret_cast<const float4*>(Up + 256));
                    float4 u3 = __ldcg(reinterpret_cast<const float4*>(Up + 384));
                    float4 cg = make_float4(0.f, 0.f, 0.f, 0.f);
                    if (Cprev)
                        cg = __ldcg(reinterpret_cast<const float4*>(
                                 Cprev + ((size_t)b * NN + m) * HD + lane * 4));
                    float cn, hn;
                    gate4(v0.x+u0.x, v1.x+u1.x, v2.x+u2.x, v3.x+u3.x, cg.x, cn, hn);
                    cmax.x = fmaxf(cmax.x, cn); hmax.x = fmaxf(hmax.x, hn);
                    gate4(v0.y+u0.y, v1.y+u1.y, v2.y+u2.y, v3.y+u3.y, cg.y, cn, hn);
                    cmax.y = fmaxf(cmax.y, cn); hmax.y = fmaxf(hmax.y, hn);
                    gate4(v0.z+u0.z, v1.z+u1.z, v2.z+u2.z, v3.z+u3.z, cg.z, cn, hn);
                    cmax.z = fmaxf(cmax.z, cn); hmax.z = fmaxf(hmax.z, hn);
                    gate4(v0.w+u0.w, v1.w+u1.w, v2.w+u2.w, v3.w+u3.w, cg.w, cn, hn);
                    cmax.w = fmaxf(cmax.w, cn); hmax.w = fmaxf(hmax.w, hn);
                }
                size_t o = ((size_t)b * NN + n) * HD + lane * 4;
                *reinterpret_cast<float4*>(Hout + o) = hmax;
                *reinterpret_cast<float4*>(Cout + o) = cmax;
            }
        }

        grid_barrier();
    }
}

// ---------------- output assembly ----------------
__global__ void out1_pos_kernel(const float* __restrict__ x, float* __restrict__ out) {
    int i = blockIdx.x * 256 + threadIdx.x;  // B*T*4*N = 524288
    if (i < BB*TT*4*NN) {
        int bt = i >> 12;
        int r  = i & 4095;
        out[(size_t)bt * 132 * NN + r] = x[i];
    }
}

__global__ void out1_hs_kernel(float* __restrict__ out) {
    __shared__ float tile[32][33];
    int n0 = blockIdx.x * 32, j0 = blockIdx.y * 32, bt = blockIdx.z;
    int b = bt >> 5, t = bt & 31;
    int tx = threadIdx.x, ty = threadIdx.y;
    tile[ty][tx] = g_hs1[(((size_t)t*BB + b) * NN + n0 + ty) * HD + j0 + tx];
    __syncthreads();
    out[((size_t)bt * 132 + 4 + j0 + ty) * NN + n0 + tx] = tile[tx][ty];
}

__global__ void hc_kernel(float* __restrict__ out) {
    __shared__ float th[32][33];
    __shared__ float tc[32][33];
    int n0 = blockIdx.x * 32, j0 = blockIdx.y * 32, b = blockIdx.z;
    int tx = threadIdx.x, ty = threadIdx.y;
    th[ty][tx] = g_hs1[(((size_t)(TT-1)*BB + b) * NN + n0 + ty) * HD + j0 + tx];
    tc[ty][tx] = g_c[(TT-1) & 1][((size_t)b * NN + n0 + ty) * HD + j0 + tx];
    __syncthreads();
    size_t dst = ((size_t)b * HD + j0 + ty) * NN + n0 + tx;
    out[OFF_H + dst] = th[tx][ty];
    out[OFF_C + dst] = tc[tx][ty];
}

__global__ void idxf_kernel(float* __restrict__ out) {
    int i = blockIdx.x * 256 + threadIdx.x;  // 2,097,152
    out[OFF_I + i] = (float)g_idx[i];
}

// ---------------- launch ----------------
extern "C" void kernel_launch(void* const* d_in, const int* in_sizes, int n_in,
                              void* d_out, int out_size) {
    const float* x  = (const float*)d_in[0];
    const float* w0 = (const float*)d_in[1];
    const float* b0 = (const float*)d_in[2];
    const float* w1 = (const float*)d_in[3];
    const float* b1 = (const float*)d_in[4];
    float* out = (float*)d_out;

    knn_kernel<<<dim3(4, TT, BB), 256>>>(x);
    wdiff_kernel<<<4, 128>>>(w0, w1);

    dim3 gv(8, 16, BB*TT);   // batched V gemm: 64o x 64m tiles (R10 form)

    vgemm_kernel<<<gv, 256>>>(0, x, b0, w1, b1);   // V0, all t (pos only)
    layer_kernel<<<LBLK, 512>>>(0, x, w0, w1);     // layer 0: full recurrence
    vgemm_kernel<<<gv, 256>>>(1, x, b0, w1, b1);   // V1, all t (needs hs0)
    layer_kernel<<<LBLK, 512>>>(1, x, w0, w1);     // layer 1: full recurrence

    out1_pos_kernel<<<2048, 256>>>(x, out);
    out1_hs_kernel<<<dim3(32, 4, BB*TT), dim3(32, 32)>>>(out);
    hc_kernel<<<dim3(32, 4, BB), dim3(32, 32)>>>(out);
    idxf_kernel<<<8192, 256>>>(out);
}

// round 13
// speedup vs baseline: 1.3539x; 1.1046x over previous
#include <cuda_runtime.h>
#include <cstdint>
#include <cstddef>

#define BB 4
#define TT 32
#define NN 1024
#define KK 16
#define HD 128

// d_out layout (float32, concatenated outputs):
//   out1: [B][T][132][N]      17,301,504
//   h:    [B][128][N]            524,288   @ 17,301,504
//   c:    [B][128][N]            524,288   @ 17,825,792
//   gidx: [B][T][N][K] (cast)  2,097,152   @ 18,350,080
#define OFF_H 17301504
#define OFF_C 17825792
#define OFF_I 18350080

#define SBT   (BB*NN*HD)           // per-timestep h/c slab: 524288 floats
#define VSLAB ((size_t)BB*NN*512)  // per-timestep V slab: 2M floats
#define LBLK  128                  // persistent grid: 1 block/SM, 512 threads

// ---------------- device scratch (static, allowed) ----------------
// g_U and g_V* hold EXP-TRANSFORMED pre-activations:
//   gates i,f,o: exp(-val), gate g: exp(-2*val), clamped exponent <= 40.
__device__ float g_U[BB*NN*512];
__device__ float g_V0[(size_t)TT*VSLAB];      // V layer0, all t (exp-transformed)
__device__ float g_V1[(size_t)TT*VSLAB];      // V layer1, all t (exp-transformed)
__device__ float g_hs0[(size_t)TT*BB*NN*HD];  // [t][b][n][j]
__device__ float g_hs1[(size_t)TT*BB*NN*HD];
__device__ float g_c[2][BB*NN*HD];            // ping-pong, [b][n][j]
__device__ int   g_idx[BB*TT*NN*KK];
__device__ float g_Wd0[512*4];
__device__ float g_Wd1[512*4];

// ---------------- software grid barrier ----------------
__device__ unsigned g_bar_cnt = 0;
__device__ volatile unsigned g_bar_gen = 0;

__device__ __forceinline__ void grid_barrier() {
    __threadfence();          // flush this thread's global writes
    __syncthreads();
    if (threadIdx.x == 0) {
        unsigned gen = g_bar_gen;
        if (atomicAdd(&g_bar_cnt, 1) == (unsigned)(gridDim.x - 1)) {
            g_bar_cnt = 0;
            __threadfence();
            g_bar_gen = gen + 1;   // release
        } else {
            while (g_bar_gen == gen) __nanosleep(64);
        }
    }
    __syncthreads();
}

// ---------------- gate math on exp-transformed inputs ----------------
// Inputs: ea=exp(-gi), ef=exp(-gf), ec=exp(-go), eb=exp(-2gg)  (as products
// of the per-point U and V factors). 1 exp + 3 rcp per element.
//   sig(gi)*tanh(gg) = (1-eb)/((1+ea)(1+eb))
//   sig(gf)*cg       = cg/(1+ef)
//   sig(go)*tanh(cn) = (1-ed)/((1+ec)(1+ed)),  ed=exp(-2cn)
__device__ __forceinline__ void gate4e(
    float ea, float ef, float ec, float eb, float cg,
    float& cn_out, float& hn_out)
{
    float it = __fdividef(1.0f - eb, (1.0f + ea) * (1.0f + eb));
    float sf = __fdividef(cg, 1.0f + ef);
    float cn = it + sf;
    float ed = __expf(fminf(-2.0f * cn, 80.f));
    float hn = __fdividef(1.0f - ed, (1.0f + ec) * (1.0f + ed));
    cn_out = cn; hn_out = hn;
}

// exp-transform for a pre-activation belonging to gate `g` (0=i,1=f,2=o,3=g)
__device__ __forceinline__ float exp_xform(float v, int gate3) {
    float s = gate3 ? -2.0f : -1.0f;
    return __expf(fminf(s * v, 40.f));
}

// ---------------- KNN: stable top-16 smallest d2 ----------------
// Rounding matches XLA's fp32 emission:
//   q2/r2: separate mul + add (NO fma contraction); qr: fma chain from 0;
//   d2: fl( fl(q2 + r2) - 2*qr )
__global__ __launch_bounds__(256) void knn_kernel(const float* __restrict__ x) {
    __shared__ float rx[NN], ry[NN], rz[NN], rr[NN];
    int t = blockIdx.y, b = blockIdx.z;
    int f = t ? t - 1 : 0;
    const float* rb = x + ((size_t)(b*TT + f) * 4) * NN;
    for (int i = threadIdx.x; i < NN; i += 256) {
        float a = rb[i], bb = rb[NN + i], cc = rb[2*NN + i];
        rx[i] = a; ry[i] = bb; rz[i] = cc;
        float s = __fadd_rn(__fmul_rn(a, a), __fmul_rn(bb, bb));
        rr[i] = __fadd_rn(s, __fmul_rn(cc, cc));
    }
    __syncthreads();

    int n = blockIdx.x * 256 + threadIdx.x;
    const float* qb = x + ((size_t)(b*TT + t) * 4) * NN;
    float qx = qb[n], qy = qb[NN + n], qz = qb[2*NN + n];
    float q2 = __fadd_rn(__fadd_rn(__fmul_rn(qx, qx), __fmul_rn(qy, qy)),
                         __fmul_rn(qz, qz));

    float bd[KK]; int bi[KK];
#pragma unroll
    for (int k = 0; k < KK; ++k) { bd[k] = 3.402823466e38f; bi[k] = 0; }

    for (int m = 0; m < NN; ++m) {
        float qr = __fmaf_rn(qz, rz[m],
                    __fmaf_rn(qy, ry[m],
                     __fmaf_rn(qx, rx[m], 0.0f)));
        float d  = __fsub_rn(__fadd_rn(q2, rr[m]), __fmul_rn(2.0f, qr));
        if (d < bd[KK-1]) {
            bd[KK-1] = d; bi[KK-1] = m;
#pragma unroll
            for (int jj = KK-1; jj > 0; --jj) {
                if (bd[jj] < bd[jj-1]) {
                    float td = bd[jj]; bd[jj] = bd[jj-1]; bd[jj-1] = td;
                    int   ti = bi[jj]; bi[jj] = bi[jj-1]; bi[jj-1] = ti;
                }
            }
        }
    }
    int* op = g_idx + (((size_t)b*TT + t) * NN + n) * KK;
#pragma unroll
    for (int k = 0; k < KK; ++k) op[k] = bi[k];
}

// ---------------- weight prep: Wd = Wx[:, :4] - Wpd ----------------
__global__ void wdiff_kernel(const float* __restrict__ w0, const float* __restrict__ w1) {
    int o = blockIdx.x * 128 + threadIdx.x;
    if (o < 512) {
#pragma unroll
        for (int c = 0; c < 4; ++c) {
            g_Wd0[o*4 + c] = w0[o*136 + c] - w0[o*136 + 4 + c];
            g_Wd1[o*4 + c] = w1[o*264 + c] - w1[o*264 + 132 + c];
        }
    }
}

// ---------------- batched V GEMM -> exp-transformed V ----------------
// mode 0: V0 = Wd0*pos + b0 (pos only);  mode 1: V1 = Wd1*pos + Wh*hs0(t) + b1
// Tile 64o x 64m, 256 threads, thread = 4o x 4m. Epilogue applies exp_xform.
__global__ __launch_bounds__(256) void vgemm_kernel(
    int mode,
    const float* __restrict__ x,
    const float* __restrict__ b0,
    const float* __restrict__ w1, const float* __restrict__ b1)
{
    int b = blockIdx.z & 3, tt = blockIdx.z >> 2;

    const float* Wp   = mode ? g_Wd1 : g_Wd0;
    const float* bias = mode ? b1 : b0;
    const float* Wh   = mode ? (w1 + 4) : nullptr;
    const int    ldh  = 264;
    const float* H    = mode ? (g_hs0 + (size_t)tt * SBT) : nullptr;
    float* Out        = (mode ? g_V1 : g_V0) + (size_t)tt * VSLAB;

    __shared__ float sWp[4][64];
    __shared__ float sP [4][64];
    __shared__ float sW [16][68];
    __shared__ float sIn[16][68];

    int tid = threadIdx.x;
    int o0  = blockIdx.x * 64;
    int m0  = blockIdx.y * 64;
    int of  = (tid & 15) * 4;
    int mf  = (tid >> 4) * 4;
    int gate3 = (blockIdx.x >> 1) == 3;   // gate id = o0/128

    const float* Pb = x + ((size_t)(b*TT + tt) * 4) * NN + m0;
    {
        int c = tid >> 6, mm = tid & 63;
        sP[c][mm]  = Pb[(size_t)c * NN + mm];
        sWp[c][mm] = Wp[(size_t)(o0 + mm) * 4 + c];
    }
    __syncthreads();

    float acc[4][4];
    {
        float bv0 = bias[o0+of], bv1 = bias[o0+of+1], bv2 = bias[o0+of+2], bv3 = bias[o0+of+3];
#pragma unroll
        for (int mi = 0; mi < 4; ++mi) { acc[mi][0]=bv0; acc[mi][1]=bv1; acc[mi][2]=bv2; acc[mi][3]=bv3; }
    }

#pragma unroll
    for (int c = 0; c < 4; ++c) {
        float a0 = sWp[c][of], a1 = sWp[c][of+1], a2 = sWp[c][of+2], a3 = sWp[c][of+3];
#pragma unroll
        for (int mi = 0; mi < 4; ++mi) {
            float p = sP[c][mf + mi];
            acc[mi][0] = fmaf(a0, p, acc[mi][0]);
            acc[mi][1] = fmaf(a1, p, acc[mi][1]);
            acc[mi][2] = fmaf(a2, p, acc[mi][2]);
            acc[mi][3] = fmaf(a3, p, acc[mi][3]);
        }
    }

    if (Wh && H) {
        const float* Hb = H + ((size_t)b * NN + m0) * HD;
        int rr4 = tid >> 2;
        int k4  = (tid & 3) * 4;
        for (int k0 = 0; k0 < HD; k0 += 16) {
            {
                float4 wv = *reinterpret_cast<const float4*>(Wh + (size_t)(o0 + rr4) * ldh + k0 + k4);
                sW[k4  ][rr4] = wv.x; sW[k4+1][rr4] = wv.y;
                sW[k4+2][rr4] = wv.z; sW[k4+3][rr4] = wv.w;
            }
            {
                float4 hv = *reinterpret_cast<const float4*>(Hb + (size_t)rr4 * HD + k0 + k4);
                sIn[k4  ][rr4] = hv.x; sIn[k4+1][rr4] = hv.y;
                sIn[k4+2][rr4] = hv.z; sIn[k4+3][rr4] = hv.w;
            }
            __syncthreads();
#pragma unroll
            for (int k = 0; k < 16; ++k) {
                float4 a = *reinterpret_cast<const float4*>(&sW[k][of]);
                float4 p = *reinterpret_cast<const float4*>(&sIn[k][mf]);
                float pb[4] = {p.x, p.y, p.z, p.w};
#pragma unroll
                for (int mi = 0; mi < 4; ++mi) {
                    acc[mi][0] = fmaf(a.x, pb[mi], acc[mi][0]);
                    acc[mi][1] = fmaf(a.y, pb[mi], acc[mi][1]);
                    acc[mi][2] = fmaf(a.z, pb[mi], acc[mi][2]);
                    acc[mi][3] = fmaf(a.w, pb[mi], acc[mi][3]);
                }
            }
            __syncthreads();
        }
    }

    float* Ob = Out + ((size_t)b * NN + m0 + mf) * 512 + o0 + of;
#pragma unroll
    for (int mi = 0; mi < 4; ++mi) {
        float4 v = make_float4(exp_xform(acc[mi][0], gate3),
                               exp_xform(acc[mi][1], gate3),
                               exp_xform(acc[mi][2], gate3),
                               exp_xform(acc[mi][3], gate3));
        *reinterpret_cast<float4*>(Ob + (size_t)mi * 512) = v;
    }
}

// ---------------- persistent per-layer kernel: full 32-step recurrence ------
// Grid 128 x 512 threads: exactly 1 block/SM -> uniform barrier arrival.
// Phase A: U = Wp*pos + Wh*h_prev, then exp-transform. 128 tiles of
//   128o x 128m (one gate per block: gate = blockIdx.x & 3), 1 per block.
//   Thread = 8o x 4m with SPLIT o-columns (of and of+64): conflict-free LDS.
// Phase B: gate (1 exp + 3 rcp per element) + max-over-K; 2 points/warp.
__global__ __launch_bounds__(512, 1) void layer_kernel(
    int layer, const float* __restrict__ x,
    const float* __restrict__ w0, const float* __restrict__ w1)
{
    const float* Wp = layer ? (w1 + 132) : (w0 + 4);
    const float* Wh = layer ? (w1 + 136) : (w0 + 8);
    const int    ldw = layer ? 264 : 136;
    const float* Vbase = layer ? g_V1 : g_V0;
    float*       Hs    = layer ? g_hs1 : g_hs0;

    __shared__ float sWp[4][128];
    __shared__ float sP [4][128];
    __shared__ float sW [32][132];
    __shared__ float sIn[32][132];

    int tid  = threadIdx.x;
    int warp = tid >> 5, lane = tid & 31;

    // tile assignment: 4 o-tiles x 8 m-tiles x 4 b = 128 = gridDim
    int o0 = (blockIdx.x & 3) * 128;
    int m0 = ((blockIdx.x >> 2) & 7) * 128;
    int bA = blockIdx.x >> 5;
    int of = (tid & 15) * 4;     // columns of..of+3 and of+64..of+67
    int mf = (tid >> 4) * 4;     // 4 points
    int gate3 = (blockIdx.x & 3) == 3;

    for (int t = 0; t < TT; ++t) {
        int frame = t ? t - 1 : 0;
        const float* Hprev = t ? (Hs + (size_t)(t-1) * SBT) : nullptr;

        // ---------------- Phase A: U (exp-transformed) ----------------
        {
            const float* Pb = x + ((size_t)(bA*TT + frame) * 4) * NN + m0;
            {
                int c = tid >> 7, mm = tid & 127;
                sWp[c][mm] = Wp[(size_t)(o0 + mm) * ldw + c];
                sP[c][mm]  = Pb[(size_t)c * NN + mm];
            }
            __syncthreads();

            float acc[4][8];
#pragma unroll
            for (int mi = 0; mi < 4; ++mi)
#pragma unroll
                for (int oi = 0; oi < 8; ++oi) acc[mi][oi] = 0.f;

#pragma unroll
            for (int c = 0; c < 4; ++c) {
                float a[8];
#pragma unroll
                for (int oi = 0; oi < 4; ++oi) {
                    a[oi]   = sWp[c][of + oi];
                    a[oi+4] = sWp[c][64 + of + oi];
                }
#pragma unroll
                for (int mi = 0; mi < 4; ++mi) {
                    float p = sP[c][mf + mi];
#pragma unroll
                    for (int oi = 0; oi < 8; ++oi)
                        acc[mi][oi] = fmaf(a[oi], p, acc[mi][oi]);
                }
            }

            if (Hprev) {
                const float* Hb = Hprev + ((size_t)bA * NN + m0) * HD;
                for (int k0 = 0; k0 < HD; k0 += 32) {
#pragma unroll
                    for (int rep = 0; rep < 2; ++rep) {   // 1024 float4 / 512 thr
                        int i = tid + rep * 512;
                        int row = i >> 3, kq = (i & 7) * 4;
                        float4 wv = *reinterpret_cast<const float4*>(
                            Wh + (size_t)(o0 + row) * ldw + k0 + kq);
                        sW[kq  ][row] = wv.x; sW[kq+1][row] = wv.y;
                        sW[kq+2][row] = wv.z; sW[kq+3][row] = wv.w;
                        // h written by other blocks last step -> L2-coherent
                        float4 hv = __ldcg(reinterpret_cast<const float4*>(
                            Hb + (size_t)row * HD + k0 + kq));
                        sIn[kq  ][row] = hv.x; sIn[kq+1][row] = hv.y;
                        sIn[kq+2][row] = hv.z; sIn[kq+3][row] = hv.w;
                    }
                    __syncthreads();
#pragma unroll
                    for (int k = 0; k < 32; ++k) {
                        float4 a0 = *reinterpret_cast<const float4*>(&sW[k][of]);
                        float4 a1 = *reinterpret_cast<const float4*>(&sW[k][64 + of]);
                        float aa[8] = {a0.x,a0.y,a0.z,a0.w,a1.x,a1.y,a1.z,a1.w};
                        float4 p = *reinterpret_cast<const float4*>(&sIn[k][mf]);
                        float pb[4] = {p.x, p.y, p.z, p.w};
#pragma unroll
                        for (int mi = 0; mi < 4; ++mi)
#pragma unroll
                            for (int oi = 0; oi < 8; ++oi)
                                acc[mi][oi] = fmaf(aa[oi], pb[mi], acc[mi][oi]);
                    }
                    __syncthreads();
                }
            }

            float* Ob = g_U + ((size_t)bA * NN + m0 + mf) * 512 + o0 + of;
#pragma unroll
            for (int mi = 0; mi < 4; ++mi) {
                *reinterpret_cast<float4*>(Ob + (size_t)mi * 512) =
                    make_float4(exp_xform(acc[mi][0], gate3), exp_xform(acc[mi][1], gate3),
                                exp_xform(acc[mi][2], gate3), exp_xform(acc[mi][3], gate3));
                *reinterpret_cast<float4*>(Ob + (size_t)mi * 512 + 64) =
                    make_float4(exp_xform(acc[mi][4], gate3), exp_xform(acc[mi][5], gate3),
                                exp_xform(acc[mi][6], gate3), exp_xform(acc[mi][7], gate3));
            }
        }

        grid_barrier();

        // ---------------- Phase B: gate + max over K ----------------
        {
            const float* Vt    = Vbase + (size_t)t * VSLAB;
            const float* Cprev = t ? g_c[(t-1) & 1] : nullptr;
            float* Hout = Hs + (size_t)t * SBT;
            float* Cout = g_c[t & 1];

            for (int p = blockIdx.x * 16 + warp; p < BB*NN; p += LBLK * 16) {
                int b = p >> 10, n = p & 1023;
                int mreg = 0;
                if (lane < KK)
                    mreg = g_idx[(((size_t)b*TT + t) * NN + n) * KK + lane];

                const float* Vp = Vt + ((size_t)b * NN + n) * 512 + lane * 4;
                float4 v0 = *reinterpret_cast<const float4*>(Vp);        // exp(-Vi)
                float4 v1 = *reinterpret_cast<const float4*>(Vp + 128);  // exp(-Vf)
                float4 v2 = *reinterpret_cast<const float4*>(Vp + 256);  // exp(-Vo)
                float4 v3 = *reinterpret_cast<const float4*>(Vp + 384);  // exp(-2Vg)

                float4 hmax = make_float4(-1e30f,-1e30f,-1e30f,-1e30f);
                float4 cmax = hmax;
#pragma unroll 4
                for (int k = 0; k < KK; ++k) {
                    int m = __shfl_sync(0xffffffffu, mreg, k);
                    const float* Up = g_U + ((size_t)b * NN + m) * 512 + lane * 4;
                    float4 u0 = __ldcg(reinterpret_cast<const float4*>(Up));
                    float4 u1 = __ldcg(reinterpret_cast<const float4*>(Up + 128));
                    float4 u2 = __ldcg(reinterpret_cast<const float4*>(Up + 256));
                    float4 u3 = __ldcg(reinterpret_cast<const float4*>(Up + 384));
                    float4 cg = make_float4(0.f, 0.f, 0.f, 0.f);
                    if (Cprev)
                        cg = __ldcg(reinterpret_cast<const float4*>(
                                 Cprev + ((size_t)b * NN + m) * HD + lane * 4));
                    float cn, hn;
                    gate4e(v0.x*u0.x, v1.x*u1.x, v2.x*u2.x, v3.x*u3.x, cg.x, cn, hn);
                    cmax.x = fmaxf(cmax.x, cn); hmax.x = fmaxf(hmax.x, hn);
                    gate4e(v0.y*u0.y, v1.y*u1.y, v2.y*u2.y, v3.y*u3.y, cg.y, cn, hn);
                    cmax.y = fmaxf(cmax.y, cn); hmax.y = fmaxf(hmax.y, hn);
                    gate4e(v0.z*u0.z, v1.z*u1.z, v2.z*u2.z, v3.z*u3.z, cg.z, cn, hn);
                    cmax.z = fmaxf(cmax.z, cn); hmax.z = fmaxf(hmax.z, hn);
                    gate4e(v0.w*u0.w, v1.w*u1.w, v2.w*u2.w, v3.w*u3.w, cg.w, cn, hn);
                    cmax.w = fmaxf(cmax.w, cn); hmax.w = fmaxf(hmax.w, hn);
                }
                size_t o = ((size_t)b * NN + n) * HD + lane * 4;
                *reinterpret_cast<float4*>(Hout + o) = hmax;
                *reinterpret_cast<float4*>(Cout + o) = cmax;
            }
        }

        grid_barrier();
    }
}

// ---------------- output assembly ----------------
__global__ void out1_pos_kernel(const float* __restrict__ x, float* __restrict__ out) {
    int i = blockIdx.x * 256 + threadIdx.x;  // B*T*4*N = 524288
    if (i < BB*TT*4*NN) {
        int bt = i >> 12;
        int r  = i & 4095;
        out[(size_t)bt * 132 * NN + r] = x[i];
    }
}

__global__ void out1_hs_kernel(float* __restrict__ out) {
    __shared__ float tile[32][33];
    int n0 = blockIdx.x * 32, j0 = blockIdx.y * 32, bt = blockIdx.z;
    int b = bt >> 5, t = bt & 31;
    int tx = threadIdx.x, ty = threadIdx.y;
    tile[ty][tx] = g_hs1[(((size_t)t*BB + b) * NN + n0 + ty) * HD + j0 + tx];
    __syncthreads();
    out[((size_t)bt * 132 + 4 + j0 + ty) * NN + n0 + tx] = tile[tx][ty];
}

__global__ void hc_kernel(float* __restrict__ out) {
    __shared__ float th[32][33];
    __shared__ float tc[32][33];
    int n0 = blockIdx.x * 32, j0 = blockIdx.y * 32, b = blockIdx.z;
    int tx = threadIdx.x, ty = threadIdx.y;
    th[ty][tx] = g_hs1[(((size_t)(TT-1)*BB + b) * NN + n0 + ty) * HD + j0 + tx];
    tc[ty][tx] = g_c[(TT-1) & 1][((size_t)b * NN + n0 + ty) * HD + j0 + tx];
    __syncthreads();
    size_t dst = ((size_t)b * HD + j0 + ty) * NN + n0 + tx;
    out[OFF_H + dst] = th[tx][ty];
    out[OFF_C + dst] = tc[tx][ty];
}

__global__ void idxf_kernel(float* __restrict__ out) {
    int i = blockIdx.x * 256 + threadIdx.x;  // 2,097,152
    out[OFF_I + i] = (float)g_idx[i];
}

// ---------------- launch ----------------
extern "C" void kernel_launch(void* const* d_in, const int* in_sizes, int n_in,
                              void* d_out, int out_size) {
    const float* x  = (const float*)d_in[0];
    const float* w0 = (const float*)d_in[1];
    const float* b0 = (const float*)d_in[2];
    const float* w1 = (const float*)d_in[3];
    const float* b1 = (const float*)d_in[4];
    float* out = (float*)d_out;

    knn_kernel<<<dim3(4, TT, BB), 256>>>(x);
    wdiff_kernel<<<4, 128>>>(w0, w1);

    dim3 gv(8, 16, BB*TT);   // batched V gemm: 64o x 64m tiles

    vgemm_kernel<<<gv, 256>>>(0, x, b0, w1, b1);   // V0, all t (pos only)
    layer_kernel<<<LBLK, 512>>>(0, x, w0, w1);     // layer 0: full recurrence
    vgemm_kernel<<<gv, 256>>>(1, x, b0, w1, b1);   // V1, all t (needs hs0)
    layer_kernel<<<LBLK, 512>>>(1, x, w0, w1);     // layer 1: full recurrence

    out1_pos_kernel<<<2048, 256>>>(x, out);
    out1_hs_kernel<<<dim3(32, 4, BB*TT), dim3(32, 32)>>>(out);
    hc_kernel<<<dim3(32, 4, BB), dim3(32, 32)>>>(out);
    idxf_kernel<<<8192, 256>>>(out);
}

// round 14
// speedup vs baseline: 1.4053x; 1.0379x over previous
#include <cuda_runtime.h>
#include <cstdint>
#include <cstddef>

#define BB 4
#define TT 32
#define NN 1024
#define KK 16
#define HD 128

// d_out layout (float32, concatenated outputs):
//   out1: [B][T][132][N]      17,301,504
//   h:    [B][128][N]            524,288   @ 17,301,504
//   c:    [B][128][N]            524,288   @ 17,825,792
//   gidx: [B][T][N][K] (cast)  2,097,152   @ 18,350,080
#define OFF_H 17301504
#define OFF_C 17825792
#define OFF_I 18350080

#define SBT   (BB*NN*HD)           // per-timestep h/c slab: 524288 floats
#define VSLAB ((size_t)BB*NN*512)  // per-timestep V slab: 2M floats
#define LBLK  128                  // persistent grid: 1 block/SM, 512 threads

// ---------------- device scratch (static, allowed) ----------------
// g_U and g_V* hold EXP-TRANSFORMED pre-activations:
//   gates i,f,o: exp(-val), gate g: exp(-2*val), exponent clamped <= 12.5
//   (clamp is ~20 sigma out of the data distribution; it only guards inf).
__device__ float g_U[BB*NN*512];
__device__ float g_V0[(size_t)TT*VSLAB];      // V layer0, all t (exp-transformed)
__device__ float g_V1[(size_t)TT*VSLAB];      // V layer1, all t (exp-transformed)
__device__ float g_hs0[(size_t)TT*BB*NN*HD];  // [t][b][n][j]
__device__ float g_hs1[(size_t)TT*BB*NN*HD];
__device__ float g_c[2][BB*NN*HD];            // ping-pong, [b][n][j]
__device__ int   g_idx[BB*TT*NN*KK];
__device__ float g_Wd0[512*4];
__device__ float g_Wd1[512*4];

// ---------------- per-batch software barriers (32 blocks each) ----------------
__device__ unsigned g_bar_cnt4[BB] = {0, 0, 0, 0};
__device__ volatile unsigned g_bar_gen4[BB];

__device__ __forceinline__ void batch_barrier(int b) {
    __threadfence();          // flush this block's global writes
    __syncthreads();
    if (threadIdx.x == 0) {
        unsigned gen = g_bar_gen4[b];
        if (atomicAdd(&g_bar_cnt4[b], 1) == 31u) {
            g_bar_cnt4[b] = 0;
            __threadfence();
            g_bar_gen4[b] = gen + 1;   // release
        } else {
            while (g_bar_gen4[b] == gen) { }
        }
    }
    __syncthreads();
}

// ---------------- gate math on exp-transformed inputs ----------------
// ea=exp(-gi), ef=exp(-gf), ec=exp(-go), eb=exp(-2gg) as products of per-point
// U and V factors (each factor <= e^12.5, so all denominator products are
// finite in fp32). 3 MUFU per element: rcp, exp, rcp.
//   cn = [ (1-eb)*pf + cg*pa*pb ] / (pa*pb*pf),  pa=1+ea, pb=1+eb, pf=1+ef
//   hn = (1-ed) / ((1+ec)(1+ed)),                ed=exp(-2cn)
__device__ __forceinline__ void gate4e(
    float ea, float ef, float ec, float eb, float cg,
    float& cn_out, float& hn_out)
{
    float pa = 1.0f + ea, pb = 1.0f + eb, pf = 1.0f + ef;
    float num = fmaf((1.0f - eb), pf, cg * pa * pb);
    float cn  = __fdividef(num, pa * pb * pf);
    float ed  = __expf(fminf(-2.0f * cn, 25.f));
    float hn  = __fdividef(1.0f - ed, (1.0f + ec) * (1.0f + ed));
    cn_out = cn; hn_out = hn;
}

// exp-transform for a pre-activation belonging to gate `g` (0=i,1=f,2=o,3=g)
__device__ __forceinline__ float exp_xform(float v, int gate3) {
    float s = gate3 ? -2.0f : -1.0f;
    return __expf(fminf(s * v, 12.5f));
}

// ---------------- KNN: stable top-16 smallest d2 ----------------
// Rounding matches XLA's fp32 emission:
//   q2/r2: separate mul + add (NO fma contraction); qr: fma chain from 0;
//   d2: fl( fl(q2 + r2) - 2*qr )
__global__ __launch_bounds__(256) void knn_kernel(const float* __restrict__ x) {
    __shared__ float rx[NN], ry[NN], rz[NN], rr[NN];
    int t = blockIdx.y, b = blockIdx.z;
    int f = t ? t - 1 : 0;
    const float* rb = x + ((size_t)(b*TT + f) * 4) * NN;
    for (int i = threadIdx.x; i < NN; i += 256) {
        float a = rb[i], bb = rb[NN + i], cc = rb[2*NN + i];
        rx[i] = a; ry[i] = bb; rz[i] = cc;
        float s = __fadd_rn(__fmul_rn(a, a), __fmul_rn(bb, bb));
        rr[i] = __fadd_rn(s, __fmul_rn(cc, cc));
    }
    __syncthreads();

    int n = blockIdx.x * 256 + threadIdx.x;
    const float* qb = x + ((size_t)(b*TT + t) * 4) * NN;
    float qx = qb[n], qy = qb[NN + n], qz = qb[2*NN + n];
    float q2 = __fadd_rn(__fadd_rn(__fmul_rn(qx, qx), __fmul_rn(qy, qy)),
                         __fmul_rn(qz, qz));

    float bd[KK]; int bi[KK];
#pragma unroll
    for (int k = 0; k < KK; ++k) { bd[k] = 3.402823466e38f; bi[k] = 0; }

    for (int m = 0; m < NN; ++m) {
        float qr = __fmaf_rn(qz, rz[m],
                    __fmaf_rn(qy, ry[m],
                     __fmaf_rn(qx, rx[m], 0.0f)));
        float d  = __fsub_rn(__fadd_rn(q2, rr[m]), __fmul_rn(2.0f, qr));
        if (d < bd[KK-1]) {
            bd[KK-1] = d; bi[KK-1] = m;
#pragma unroll
            for (int jj = KK-1; jj > 0; --jj) {
                if (bd[jj] < bd[jj-1]) {
                    float td = bd[jj]; bd[jj] = bd[jj-1]; bd[jj-1] = td;
                    int   ti = bi[jj]; bi[jj] = bi[jj-1]; bi[jj-1] = ti;
                }
            }
        }
    }
    int* op = g_idx + (((size_t)b*TT + t) * NN + n) * KK;
#pragma unroll
    for (int k = 0; k < KK; ++k) op[k] = bi[k];
}

// ---------------- weight prep: Wd = Wx[:, :4] - Wpd ----------------
__global__ void wdiff_kernel(const float* __restrict__ w0, const float* __restrict__ w1) {
    int o = blockIdx.x * 128 + threadIdx.x;
    if (o < 512) {
#pragma unroll
        for (int c = 0; c < 4; ++c) {
            g_Wd0[o*4 + c] = w0[o*136 + c] - w0[o*136 + 4 + c];
            g_Wd1[o*4 + c] = w1[o*264 + c] - w1[o*264 + 132 + c];
        }
    }
}

// ---------------- batched V GEMM -> exp-transformed V ----------------
// mode 0: V0 = Wd0*pos + b0 (pos only);  mode 1: V1 = Wd1*pos + Wh*hs0(t) + b1
// Tile 64o x 64m, 256 threads, thread = 4o x 4m. Epilogue applies exp_xform.
__global__ __launch_bounds__(256) void vgemm_kernel(
    int mode,
    const float* __restrict__ x,
    const float* __restrict__ b0,
    const float* __restrict__ w1, const float* __restrict__ b1)
{
    int b = blockIdx.z & 3, tt = blockIdx.z >> 2;

    const float* Wp   = mode ? g_Wd1 : g_Wd0;
    const float* bias = mode ? b1 : b0;
    const float* Wh   = mode ? (w1 + 4) : nullptr;
    const int    ldh  = 264;
    const float* H    = mode ? (g_hs0 + (size_t)tt * SBT) : nullptr;
    float* Out        = (mode ? g_V1 : g_V0) + (size_t)tt * VSLAB;

    __shared__ float sWp[4][64];
    __shared__ float sP [4][64];
    __shared__ float sW [16][68];
    __shared__ float sIn[16][68];

    int tid = threadIdx.x;
    int o0  = blockIdx.x * 64;
    int m0  = blockIdx.y * 64;
    int of  = (tid & 15) * 4;
    int mf  = (tid >> 4) * 4;
    int gate3 = (blockIdx.x >> 1) == 3;   // gate id = o0/128

    const float* Pb = x + ((size_t)(b*TT + tt) * 4) * NN + m0;
    {
        int c = tid >> 6, mm = tid & 63;
        sP[c][mm]  = Pb[(size_t)c * NN + mm];
        sWp[c][mm] = Wp[(size_t)(o0 + mm) * 4 + c];
    }
    __syncthreads();

    float acc[4][4];
    {
        float bv0 = bias[o0+of], bv1 = bias[o0+of+1], bv2 = bias[o0+of+2], bv3 = bias[o0+of+3];
#pragma unroll
        for (int mi = 0; mi < 4; ++mi) { acc[mi][0]=bv0; acc[mi][1]=bv1; acc[mi][2]=bv2; acc[mi][3]=bv3; }
    }

#pragma unroll
    for (int c = 0; c < 4; ++c) {
        float a0 = sWp[c][of], a1 = sWp[c][of+1], a2 = sWp[c][of+2], a3 = sWp[c][of+3];
#pragma unroll
        for (int mi = 0; mi < 4; ++mi) {
            float p = sP[c][mf + mi];
            acc[mi][0] = fmaf(a0, p, acc[mi][0]);
            acc[mi][1] = fmaf(a1, p, acc[mi][1]);
            acc[mi][2] = fmaf(a2, p, acc[mi][2]);
            acc[mi][3] = fmaf(a3, p, acc[mi][3]);
        }
    }

    if (Wh && H) {
        const float* Hb = H + ((size_t)b * NN + m0) * HD;
        int rr4 = tid >> 2;
        int k4  = (tid & 3) * 4;
        for (int k0 = 0; k0 < HD; k0 += 16) {
            {
                float4 wv = *reinterpret_cast<const float4*>(Wh + (size_t)(o0 + rr4) * ldh + k0 + k4);
                sW[k4  ][rr4] = wv.x; sW[k4+1][rr4] = wv.y;
                sW[k4+2][rr4] = wv.z; sW[k4+3][rr4] = wv.w;
            }
            {
                float4 hv = *reinterpret_cast<const float4*>(Hb + (size_t)rr4 * HD + k0 + k4);
                sIn[k4  ][rr4] = hv.x; sIn[k4+1][rr4] = hv.y;
                sIn[k4+2][rr4] = hv.z; sIn[k4+3][rr4] = hv.w;
            }
            __syncthreads();
#pragma unroll
            for (int k = 0; k < 16; ++k) {
                float4 a = *reinterpret_cast<const float4*>(&sW[k][of]);
                float4 p = *reinterpret_cast<const float4*>(&sIn[k][mf]);
                float pb[4] = {p.x, p.y, p.z, p.w};
#pragma unroll
                for (int mi = 0; mi < 4; ++mi) {
                    acc[mi][0] = fmaf(a.x, pb[mi], acc[mi][0]);
                    acc[mi][1] = fmaf(a.y, pb[mi], acc[mi][1]);
                    acc[mi][2] = fmaf(a.z, pb[mi], acc[mi][2]);
                    acc[mi][3] = fmaf(a.w, pb[mi], acc[mi][3]);
                }
            }
            __syncthreads();
        }
    }

    float* Ob = Out + ((size_t)b * NN + m0 + mf) * 512 + o0 + of;
#pragma unroll
    for (int mi = 0; mi < 4; ++mi) {
        float4 v = make_float4(exp_xform(acc[mi][0], gate3),
                               exp_xform(acc[mi][1], gate3),
                               exp_xform(acc[mi][2], gate3),
                               exp_xform(acc[mi][3], gate3));
        *reinterpret_cast<float4*>(Ob + (size_t)mi * 512) = v;
    }
}

// ---------------- persistent per-layer kernel: full 32-step recurrence ------
// Grid 128 x 512 threads: 1 block/SM. Blocks are grouped by batch (32 each);
// ALL cross-block dependences are batch-local, so each batch runs its own
// 32-block barrier and the four recurrences proceed independently.
// Phase A: U = exp_xform(Wp*pos + Wh*h_prev). One 128o x 128m tile per block
//   (gate = blockIdx.x & 3). Thread = 8o x 4m, split o-columns: conflict-free.
// Phase B: gate (3 MUFU/elem) + max-over-K; 32 points per block (2/warp).
__global__ __launch_bounds__(512, 1) void layer_kernel(
    int layer, const float* __restrict__ x,
    const float* __restrict__ w0, const float* __restrict__ w1)
{
    const float* Wp = layer ? (w1 + 132) : (w0 + 4);
    const float* Wh = layer ? (w1 + 136) : (w0 + 8);
    const int    ldw = layer ? 264 : 136;
    const float* Vbase = layer ? g_V1 : g_V0;
    float*       Hs    = layer ? g_hs1 : g_hs0;

    __shared__ float sWp[4][128];
    __shared__ float sP [4][128];
    __shared__ float sW [32][132];
    __shared__ float sIn[32][132];

    int tid  = threadIdx.x;
    int warp = tid >> 5, lane = tid & 31;

    // tile assignment: 4 o-tiles x 8 m-tiles x 4 b = 128 = gridDim
    int o0 = (blockIdx.x & 3) * 128;
    int m0 = ((blockIdx.x >> 2) & 7) * 128;
    int bA = blockIdx.x >> 5;            // batch group (32 blocks)
    int lb = blockIdx.x & 31;            // index within batch group
    int of = (tid & 15) * 4;     // columns of..of+3 and of+64..of+67
    int mf = (tid >> 4) * 4;     // 4 points
    int gate3 = (blockIdx.x & 3) == 3;

    for (int t = 0; t < TT; ++t) {
        int frame = t ? t - 1 : 0;
        const float* Hprev = t ? (Hs + (size_t)(t-1) * SBT) : nullptr;

        // ---------------- Phase A: U (exp-transformed) ----------------
        {
            const float* Pb = x + ((size_t)(bA*TT + frame) * 4) * NN + m0;
            {
                int c = tid >> 7, mm = tid & 127;
                sWp[c][mm] = Wp[(size_t)(o0 + mm) * ldw + c];
                sP[c][mm]  = Pb[(size_t)c * NN + mm];
            }
            __syncthreads();

            float acc[4][8];
#pragma unroll
            for (int mi = 0; mi < 4; ++mi)
#pragma unroll
                for (int oi = 0; oi < 8; ++oi) acc[mi][oi] = 0.f;

#pragma unroll
            for (int c = 0; c < 4; ++c) {
                float a[8];
#pragma unroll
                for (int oi = 0; oi < 4; ++oi) {
                    a[oi]   = sWp[c][of + oi];
                    a[oi+4] = sWp[c][64 + of + oi];
                }
#pragma unroll
                for (int mi = 0; mi < 4; ++mi) {
                    float p = sP[c][mf + mi];
#pragma unroll
                    for (int oi = 0; oi < 8; ++oi)
                        acc[mi][oi] = fmaf(a[oi], p, acc[mi][oi]);
                }
            }

            if (Hprev) {
                const float* Hb = Hprev + ((size_t)bA * NN + m0) * HD;
                for (int k0 = 0; k0 < HD; k0 += 32) {
#pragma unroll
                    for (int rep = 0; rep < 2; ++rep) {   // 1024 float4 / 512 thr
                        int i = tid + rep * 512;
                        int row = i >> 3, kq = (i & 7) * 4;
                        float4 wv = *reinterpret_cast<const float4*>(
                            Wh + (size_t)(o0 + row) * ldw + k0 + kq);
                        sW[kq  ][row] = wv.x; sW[kq+1][row] = wv.y;
                        sW[kq+2][row] = wv.z; sW[kq+3][row] = wv.w;
                        // h written by other blocks last step -> L2-coherent
                        float4 hv = __ldcg(reinterpret_cast<const float4*>(
                            Hb + (size_t)row * HD + k0 + kq));
                        sIn[kq  ][row] = hv.x; sIn[kq+1][row] = hv.y;
                        sIn[kq+2][row] = hv.z; sIn[kq+3][row] = hv.w;
                    }
                    __syncthreads();
#pragma unroll
                    for (int k = 0; k < 32; ++k) {
                        float4 a0 = *reinterpret_cast<const float4*>(&sW[k][of]);
                        float4 a1 = *reinterpret_cast<const float4*>(&sW[k][64 + of]);
                        float aa[8] = {a0.x,a0.y,a0.z,a0.w,a1.x,a1.y,a1.z,a1.w};
                        float4 p = *reinterpret_cast<const float4*>(&sIn[k][mf]);
                        float pb[4] = {p.x, p.y, p.z, p.w};
#pragma unroll
                        for (int mi = 0; mi < 4; ++mi)
#pragma unroll
                            for (int oi = 0; oi < 8; ++oi)
                                acc[mi][oi] = fmaf(aa[oi], pb[mi], acc[mi][oi]);
                    }
                    __syncthreads();
                }
            }

            float* Ob = g_U + ((size_t)bA * NN + m0 + mf) * 512 + o0 + of;
#pragma unroll
            for (int mi = 0; mi < 4; ++mi) {
                *reinterpret_cast<float4*>(Ob + (size_t)mi * 512) =
                    make_float4(exp_xform(acc[mi][0], gate3), exp_xform(acc[mi][1], gate3),
                                exp_xform(acc[mi][2], gate3), exp_xform(acc[mi][3], gate3));
                *reinterpret_cast<float4*>(Ob + (size_t)mi * 512 + 64) =
                    make_float4(exp_xform(acc[mi][4], gate3), exp_xform(acc[mi][5], gate3),
                                exp_xform(acc[mi][6], gate3), exp_xform(acc[mi][7], gate3));
            }
        }

        batch_barrier(bA);

        // ---------------- Phase B: gate + max over K ----------------
        {
            const float* Vt    = Vbase + (size_t)t * VSLAB;
            const float* Cprev = t ? g_c[(t-1) & 1] : nullptr;
            float* Hout = Hs + (size_t)t * SBT;
            float* Cout = g_c[t & 1];
            int b = bA;

#pragma unroll
            for (int i = 0; i < 2; ++i) {            // 32 points/block, 2/warp
                int n = lb * 32 + warp * 2 + i;
                int mreg = 0;
                if (lane < KK)
                    mreg = g_idx[(((size_t)b*TT + t) * NN + n) * KK + lane];

                const float* Vp = Vt + ((size_t)b * NN + n) * 512 + lane * 4;
                float4 v0 = *reinterpret_cast<const float4*>(Vp);        // exp(-Vi)
                float4 v1 = *reinterpret_cast<const float4*>(Vp + 128);  // exp(-Vf)
                float4 v2 = *reinterpret_cast<const float4*>(Vp + 256);  // exp(-Vo)
                float4 v3 = *reinterpret_cast<const float4*>(Vp + 384);  // exp(-2Vg)

                float4 hmax = make_float4(-1e30f,-1e30f,-1e30f,-1e30f);
                float4 cmax = hmax;
#pragma unroll 4
                for (int k = 0; k < KK; ++k) {
                    int m = __shfl_sync(0xffffffffu, mreg, k);
                    const float* Up = g_U + ((size_t)b * NN + m) * 512 + lane * 4;
                    float4 u0 = __ldcg(reinterpret_cast<const float4*>(Up));
                    float4 u1 = __ldcg(reinterpret_cast<const float4*>(Up + 128));
                    float4 u2 = __ldcg(reinterpret_cast<const float4*>(Up + 256));
                    float4 u3 = __ldcg(reinterpret_cast<const float4*>(Up + 384));
                    float4 cg = make_float4(0.f, 0.f, 0.f, 0.f);
                    if (Cprev)
                        cg = __ldcg(reinterpret_cast<const float4*>(
                                 Cprev + ((size_t)b * NN + m) * HD + lane * 4));
                    float cn, hn;
                    gate4e(v0.x*u0.x, v1.x*u1.x, v2.x*u2.x, v3.x*u3.x, cg.x, cn, hn);
                    cmax.x = fmaxf(cmax.x, cn); hmax.x = fmaxf(hmax.x, hn);
                    gate4e(v0.y*u0.y, v1.y*u1.y, v2.y*u2.y, v3.y*u3.y, cg.y, cn, hn);
                    cmax.y = fmaxf(cmax.y, cn); hmax.y = fmaxf(hmax.y, hn);
                    gate4e(v0.z*u0.z, v1.z*u1.z, v2.z*u2.z, v3.z*u3.z, cg.z, cn, hn);
                    cmax.z = fmaxf(cmax.z, cn); hmax.z = fmaxf(hmax.z, hn);
                    gate4e(v0.w*u0.w, v1.w*u1.w, v2.w*u2.w, v3.w*u3.w, cg.w, cn, hn);
                    cmax.w = fmaxf(cmax.w, cn); hmax.w = fmaxf(hmax.w, hn);
                }
                size_t o = ((size_t)b * NN + n) * HD + lane * 4;
                *reinterpret_cast<float4*>(Hout + o) = hmax;
                *reinterpret_cast<float4*>(Cout + o) = cmax;
            }
        }

        batch_barrier(bA);
    }
}

// ---------------- output assembly ----------------
__global__ void out1_pos_kernel(const float* __restrict__ x, float* __restrict__ out) {
    int i = blockIdx.x * 256 + threadIdx.x;  // B*T*4*N = 524288
    if (i < BB*TT*4*NN) {
        int bt = i >> 12;
        int r  = i & 4095;
        out[(size_t)bt * 132 * NN + r] = x[i];
    }
}

__global__ void out1_hs_kernel(float* __restrict__ out) {
    __shared__ float tile[32][33];
    int n0 = blockIdx.x * 32, j0 = blockIdx.y * 32, bt = blockIdx.z;
    int b = bt >> 5, t = bt & 31;
    int tx = threadIdx.x, ty = threadIdx.y;
    tile[ty][tx] = g_hs1[(((size_t)t*BB + b) * NN + n0 + ty) * HD + j0 + tx];
    __syncthreads();
    out[((size_t)bt * 132 + 4 + j0 + ty) * NN + n0 + tx] = tile[tx][ty];
}

__global__ void hc_kernel(float* __restrict__ out) {
    __shared__ float th[32][33];
    __shared__ float tc[32][33];
    int n0 = blockIdx.x * 32, j0 = blockIdx.y * 32, b = blockIdx.z;
    int tx = threadIdx.x, ty = threadIdx.y;
    th[ty][tx] = g_hs1[(((size_t)(TT-1)*BB + b) * NN + n0 + ty) * HD + j0 + tx];
    tc[ty][tx] = g_c[(TT-1) & 1][((size_t)b * NN + n0 + ty) * HD + j0 + tx];
    __syncthreads();
    size_t dst = ((size_t)b * HD + j0 + ty) * NN + n0 + tx;
    out[OFF_H + dst] = th[tx][ty];
    out[OFF_C + dst] = tc[tx][ty];
}

__global__ void idxf_kernel(float* __restrict__ out) {
    int i = blockIdx.x * 256 + threadIdx.x;  // 2,097,152
    out[OFF_I + i] = (float)g_idx[i];
}

// ---------------- launch ----------------
extern "C" void kernel_launch(void* const* d_in, const int* in_sizes, int n_in,
                              void* d_out, int out_size) {
    const float* x  = (const float*)d_in[0];
    const float* w0 = (const float*)d_in[1];
    const float* b0 = (const float*)d_in[2];
    const float* w1 = (const float*)d_in[3];
    const float* b1 = (const float*)d_in[4];
    float* out = (float*)d_out;

    knn_kernel<<<dim3(4, TT, BB), 256>>>(x);
    wdiff_kernel<<<4, 128>>>(w0, w1);

    dim3 gv(8, 16, BB*TT);   // batched V gemm: 64o x 64m tiles

    vgemm_kernel<<<gv, 256>>>(0, x, b0, w1, b1);   // V0, all t (pos only)
    layer_kernel<<<LBLK, 512>>>(0, x, w0, w1);     // layer 0: full recurrence
    vgemm_kernel<<<gv, 256>>>(1, x, b0, w1, b1);   // V1, all t (needs hs0)
    layer_kernel<<<LBLK, 512>>>(1, x, w0, w1);     // layer 1: full recurrence

    out1_pos_kernel<<<2048, 256>>>(x, out);
    out1_hs_kernel<<<dim3(32, 4, BB*TT), dim3(32, 32)>>>(out);
    hc_kernel<<<dim3(32, 4, BB), dim3(32, 32)>>>(out);
    idxf_kernel<<<8192, 256>>>(out);
}

// round 15
// speedup vs baseline: 1.4423x; 1.0263x over previous
#include <cuda_runtime.h>
#include <cstdint>
#include <cstddef>

#define BB 4
#define TT 32
#define NN 1024
#define KK 16
#define HD 128

#define OFF_H 17301504
#define OFF_C 17825792
#define OFF_I 18350080

#define SBT   (BB*NN*HD)           // per-timestep h/c slab: 524288 floats
#define VSLAB ((size_t)BB*NN*512)  // per-timestep V slab: 2M floats
#define LBLK  128                  // persistent grid: 1 block/SM, 512 threads

// dynamic smem layout for layer_kernel: sW[136][136] then sH[136][136]
#define LDS_S   136                // row stride (136 % 32 == 8 -> conflict-free frags)
#define SW_OFF  0
#define SH_OFF  (136*136)
#define DYN_SMEM (2*136*136*4)     // 147,968 bytes

// ---------------- device scratch (static, allowed) ----------------
// g_U / g_V* hold EXP-TRANSFORMED pre-activations:
//   gates i,f,o: exp(-val), gate g: exp(-2*val), exponent clamped <= 12.5
__device__ float g_U[BB*NN*512];
__device__ float g_V0[(size_t)TT*VSLAB];
__device__ float g_V1[(size_t)TT*VSLAB];
__device__ float g_hs0[(size_t)TT*BB*NN*HD];  // [t][b][n][j]
__device__ float g_hs1[(size_t)TT*BB*NN*HD];
__device__ float g_c[2][BB*NN*HD];            // ping-pong, [b][n][j]
__device__ int   g_idx[BB*TT*NN*KK];
__device__ float g_Wd0[512*4];
__device__ float g_Wd1[512*4];

// ---------------- per-batch software barriers (32 blocks each) -------------
__device__ unsigned g_bar_cnt4[BB] = {0, 0, 0, 0};
__device__ volatile unsigned g_bar_gen4[BB];

__device__ __forceinline__ void batch_barrier(int b) {
    __threadfence();
    __syncthreads();
    if (threadIdx.x == 0) {
        unsigned gen = g_bar_gen4[b];
        if (atomicAdd(&g_bar_cnt4[b], 1) == 31u) {
            g_bar_cnt4[b] = 0;
            __threadfence();
            g_bar_gen4[b] = gen + 1;
        } else {
            while (g_bar_gen4[b] == gen) { }
        }
    }
    __syncthreads();
}

// ---------------- tf32 helpers ----------------
__device__ __forceinline__ unsigned f2tf32(float f) {
    unsigned u;
    asm("cvt.rna.tf32.f32 %0, %1;" : "=r"(u) : "f"(f));
    return u;
}
__device__ __forceinline__ void split_tf32(float f, unsigned& hi, unsigned& lo) {
    hi = f2tf32(f);
    float r = f - __uint_as_float(hi);
    lo = f2tf32(r);
}
__device__ __forceinline__ void mma_tf32(float* d, const unsigned* a, const unsigned* b) {
    asm volatile(
        "mma.sync.aligned.m16n8k8.row.col.f32.tf32.tf32.f32 "
        "{%0,%1,%2,%3},{%4,%5,%6,%7},{%8,%9},{%0,%1,%2,%3};"
        : "+f"(d[0]), "+f"(d[1]), "+f"(d[2]), "+f"(d[3])
        : "r"(a[0]), "r"(a[1]), "r"(a[2]), "r"(a[3]), "r"(b[0]), "r"(b[1]));
}

// ---------------- gate math on exp-transformed inputs (3 MUFU/elem) --------
__device__ __forceinline__ void gate4e(
    float ea, float ef, float ec, float eb, float cg,
    float& cn_out, float& hn_out)
{
    float pa = 1.0f + ea, pb = 1.0f + eb, pf = 1.0f + ef;
    float num = fmaf((1.0f - eb), pf, cg * pa * pb);
    float cn  = __fdividef(num, pa * pb * pf);
    float ed  = __expf(fminf(-2.0f * cn, 25.f));
    float hn  = __fdividef(1.0f - ed, (1.0f + ec) * (1.0f + ed));
    cn_out = cn; hn_out = hn;
}

__device__ __forceinline__ float exp_xform(float v, int gate3) {
    float s = gate3 ? -2.0f : -1.0f;
    return __expf(fminf(s * v, 12.5f));
}

// ---------------- KNN: stable top-16 smallest d2 (XLA-exact rounding) ------
__global__ __launch_bounds__(256) void knn_kernel(const float* __restrict__ x) {
    __shared__ float rx[NN], ry[NN], rz[NN], rr[NN];
    int t = blockIdx.y, b = blockIdx.z;
    int f = t ? t - 1 : 0;
    const float* rb = x + ((size_t)(b*TT + f) * 4) * NN;
    for (int i = threadIdx.x; i < NN; i += 256) {
        float a = rb[i], bb = rb[NN + i], cc = rb[2*NN + i];
        rx[i] = a; ry[i] = bb; rz[i] = cc;
        float s = __fadd_rn(__fmul_rn(a, a), __fmul_rn(bb, bb));
        rr[i] = __fadd_rn(s, __fmul_rn(cc, cc));
    }
    __syncthreads();

    int n = blockIdx.x * 256 + threadIdx.x;
    const float* qb = x + ((size_t)(b*TT + t) * 4) * NN;
    float qx = qb[n], qy = qb[NN + n], qz = qb[2*NN + n];
    float q2 = __fadd_rn(__fadd_rn(__fmul_rn(qx, qx), __fmul_rn(qy, qy)),
                         __fmul_rn(qz, qz));

    float bd[KK]; int bi[KK];
#pragma unroll
    for (int k = 0; k < KK; ++k) { bd[k] = 3.402823466e38f; bi[k] = 0; }

    for (int m = 0; m < NN; ++m) {
        float qr = __fmaf_rn(qz, rz[m],
                    __fmaf_rn(qy, ry[m],
                     __fmaf_rn(qx, rx[m], 0.0f)));
        float d  = __fsub_rn(__fadd_rn(q2, rr[m]), __fmul_rn(2.0f, qr));
        if (d < bd[KK-1]) {
            bd[KK-1] = d; bi[KK-1] = m;
#pragma unroll
            for (int jj = KK-1; jj > 0; --jj) {
                if (bd[jj] < bd[jj-1]) {
                    float td = bd[jj]; bd[jj] = bd[jj-1]; bd[jj-1] = td;
                    int   ti = bi[jj]; bi[jj] = bi[jj-1]; bi[jj-1] = ti;
                }
            }
        }
    }
    int* op = g_idx + (((size_t)b*TT + t) * NN + n) * KK;
#pragma unroll
    for (int k = 0; k < KK; ++k) op[k] = bi[k];
}

// ---------------- weight prep: Wd = Wx[:, :4] - Wpd ----------------
__global__ void wdiff_kernel(const float* __restrict__ w0, const float* __restrict__ w1) {
    int o = blockIdx.x * 128 + threadIdx.x;
    if (o < 512) {
#pragma unroll
        for (int c = 0; c < 4; ++c) {
            g_Wd0[o*4 + c] = w0[o*136 + c] - w0[o*136 + 4 + c];
            g_Wd1[o*4 + c] = w1[o*264 + c] - w1[o*264 + 132 + c];
        }
    }
}

// ---------------- batched V GEMM -> exp-transformed V (fp32, known-good) ---
__global__ __launch_bounds__(256) void vgemm_kernel(
    int mode,
    const float* __restrict__ x,
    const float* __restrict__ b0,
    const float* __restrict__ w1, const float* __restrict__ b1)
{
    int b = blockIdx.z & 3, tt = blockIdx.z >> 2;

    const float* Wp   = mode ? g_Wd1 : g_Wd0;
    const float* bias = mode ? b1 : b0;
    const float* Wh   = mode ? (w1 + 4) : nullptr;
    const int    ldh  = 264;
    const float* H    = mode ? (g_hs0 + (size_t)tt * SBT) : nullptr;
    float* Out        = (mode ? g_V1 : g_V0) + (size_t)tt * VSLAB;

    __shared__ float sWp[4][64];
    __shared__ float sP [4][64];
    __shared__ float sW [16][68];
    __shared__ float sIn[16][68];

    int tid = threadIdx.x;
    int o0  = blockIdx.x * 64;
    int m0  = blockIdx.y * 64;
    int of  = (tid & 15) * 4;
    int mf  = (tid >> 4) * 4;
    int gate3 = (blockIdx.x >> 1) == 3;

    const float* Pb = x + ((size_t)(b*TT + tt) * 4) * NN + m0;
    {
        int c = tid >> 6, mm = tid & 63;
        sP[c][mm]  = Pb[(size_t)c * NN + mm];
        sWp[c][mm] = Wp[(size_t)(o0 + mm) * 4 + c];
    }
    __syncthreads();

    float acc[4][4];
    {
        float bv0 = bias[o0+of], bv1 = bias[o0+of+1], bv2 = bias[o0+of+2], bv3 = bias[o0+of+3];
#pragma unroll
        for (int mi = 0; mi < 4; ++mi) { acc[mi][0]=bv0; acc[mi][1]=bv1; acc[mi][2]=bv2; acc[mi][3]=bv3; }
    }

#pragma unroll
    for (int c = 0; c < 4; ++c) {
        float a0 = sWp[c][of], a1 = sWp[c][of+1], a2 = sWp[c][of+2], a3 = sWp[c][of+3];
#pragma unroll
        for (int mi = 0; mi < 4; ++mi) {
            float p = sP[c][mf + mi];
            acc[mi][0] = fmaf(a0, p, acc[mi][0]);
            acc[mi][1] = fmaf(a1, p, acc[mi][1]);
            acc[mi][2] = fmaf(a2, p, acc[mi][2]);
            acc[mi][3] = fmaf(a3, p, acc[mi][3]);
        }
    }

    if (Wh && H) {
        const float* Hb = H + ((size_t)b * NN + m0) * HD;
        int rr4 = tid >> 2;
        int k4  = (tid & 3) * 4;
        for (int k0 = 0; k0 < HD; k0 += 16) {
            {
                float4 wv = *reinterpret_cast<const float4*>(Wh + (size_t)(o0 + rr4) * ldh + k0 + k4);
                sW[k4  ][rr4] = wv.x; sW[k4+1][rr4] = wv.y;
                sW[k4+2][rr4] = wv.z; sW[k4+3][rr4] = wv.w;
            }
            {
                float4 hv = *reinterpret_cast<const float4*>(Hb + (size_t)rr4 * HD + k0 + k4);
                sIn[k4  ][rr4] = hv.x; sIn[k4+1][rr4] = hv.y;
                sIn[k4+2][rr4] = hv.z; sIn[k4+3][rr4] = hv.w;
            }
            __syncthreads();
#pragma unroll
            for (int k = 0; k < 16; ++k) {
                float4 a = *reinterpret_cast<const float4*>(&sW[k][of]);
                float4 p = *reinterpret_cast<const float4*>(&sIn[k][mf]);
                float pb[4] = {p.x, p.y, p.z, p.w};
#pragma unroll
                for (int mi = 0; mi < 4; ++mi) {
                    acc[mi][0] = fmaf(a.x, pb[mi], acc[mi][0]);
                    acc[mi][1] = fmaf(a.y, pb[mi], acc[mi][1]);
                    acc[mi][2] = fmaf(a.z, pb[mi], acc[mi][2]);
                    acc[mi][3] = fmaf(a.w, pb[mi], acc[mi][3]);
                }
            }
            __syncthreads();
        }
    }

    float* Ob = Out + ((size_t)b * NN + m0 + mf) * 512 + o0 + of;
#pragma unroll
    for (int mi = 0; mi < 4; ++mi) {
        float4 v = make_float4(exp_xform(acc[mi][0], gate3),
                               exp_xform(acc[mi][1], gate3),
                               exp_xform(acc[mi][2], gate3),
                               exp_xform(acc[mi][3], gate3));
        *reinterpret_cast<float4*>(Ob + (size_t)mi * 512) = v;
    }
}

// ---------------- persistent per-layer kernel (tf32 tensor-core Phase A) ---
// Grid 128 x 512, 1 block/SM, per-batch barriers (32 blocks each).
// Phase A: U = exp_xform(W * [pos; h_prev]) via 3xTF32 mma.sync.m16n8k8.
//   K = 136 (4 pos + 128 h + 4 zero pad). W tile persists in dynamic smem
//   (k-major, row stride 136). h tile loaded k-major each step.
//   16 warps: warp = (wr = w&3) o-32-block x (wc = w>>2) m-32-block;
//   each warp: 2 (16-row o) x 4 (8-col m) mma tiles.
// Phase B: gate + max-over-K (unchanged from R14).
__global__ __launch_bounds__(512, 1) void layer_kernel(
    int layer, const float* __restrict__ x,
    const float* __restrict__ w0, const float* __restrict__ w1)
{
    extern __shared__ float dyn[];
    float* sW = dyn + SW_OFF;   // [k][o], 136 x 136
    float* sH = dyn + SH_OFF;   // [k][m], 136 x 136

    const float* Wbase = layer ? (w1 + 132) : (w0 + 4);  // cols: 4 pos then 128 h
    const int    ldw   = layer ? 264 : 136;
    const float* Vbase = layer ? g_V1 : g_V0;
    float*       Hs    = layer ? g_hs1 : g_hs0;

    int tid  = threadIdx.x;
    int warp = tid >> 5, lane = tid & 31;
    int tg   = lane & 3;         // thread-in-group (k / col selector)
    int gq   = lane >> 2;        // group id (row selector, 0..7)

    int o0 = (blockIdx.x & 3) * 128;
    int m0 = ((blockIdx.x >> 2) & 7) * 128;
    int bA = blockIdx.x >> 5;
    int lb = blockIdx.x & 31;
    int gate3 = (blockIdx.x & 3) == 3;

    int o_off = (warp & 3) * 32;     // warp o block
    int m_off = (warp >> 2) * 32;    // warp m block

    // ---- one-time init: load W tile (zero-padded), zero sH ----
    for (int i = tid; i < 136 * 136; i += 512) {
        int k = i / 136, o = i - k * 136;
        float v = 0.f;
        if (k < 132 && o < 128) v = Wbase[(size_t)(o0 + o) * ldw + k];
        sW[i] = v;
        sH[i] = 0.f;
    }
    __syncthreads();

    for (int t = 0; t < TT; ++t) {
        int frame = t ? t - 1 : 0;
        const float* Hprev = t ? (Hs + (size_t)(t-1) * SBT) : nullptr;

        // ---------------- Phase A: load [pos; h] tile, k-major ----------------
        {   // pos rows 0..3
            int c = tid >> 7, m = tid & 127;
            sH[c * LDS_S + m] = x[((size_t)(bA*TT + frame) * 4 + c) * NN + m0 + m];
        }
        if (Hprev) {   // h rows 4..131
            const float* Hb = Hprev + ((size_t)bA * NN + m0) * HD;
#pragma unroll
            for (int rep = 0; rep < 8; ++rep) {
                int i = tid + rep * 512;           // 0..4095
                int m = i & 127, j4 = (i >> 7) * 4;
                float4 hv = __ldcg(reinterpret_cast<const float4*>(Hb + (size_t)m * HD + j4));
                sH[(4 + j4    ) * LDS_S + m] = hv.x;
                sH[(4 + j4 + 1) * LDS_S + m] = hv.y;
                sH[(4 + j4 + 2) * LDS_S + m] = hv.z;
                sH[(4 + j4 + 3) * LDS_S + m] = hv.w;
            }
        }
        __syncthreads();

        // ---------------- Phase A: 3xTF32 mma over K=136 ----------------
        {
            float acc[2][4][4];
#pragma unroll
            for (int ot = 0; ot < 2; ++ot)
#pragma unroll
                for (int nt = 0; nt < 4; ++nt)
#pragma unroll
                    for (int e = 0; e < 4; ++e) acc[ot][nt][e] = 0.f;

            for (int ks = 0; ks < 17; ++ks) {
                int k0 = ks * 8;
                unsigned Ahi[2][4], Alo[2][4], Bhi[4][2], Blo[4][2];
#pragma unroll
                for (int ot = 0; ot < 2; ++ot) {
                    int ob = o_off + ot * 16;
                    float f0 = sW[(k0 + tg    ) * LDS_S + ob + gq    ];
                    float f1 = sW[(k0 + tg    ) * LDS_S + ob + 8 + gq];
                    float f2 = sW[(k0 + tg + 4) * LDS_S + ob + gq    ];
                    float f3 = sW[(k0 + tg + 4) * LDS_S + ob + 8 + gq];
                    split_tf32(f0, Ahi[ot][0], Alo[ot][0]);
                    split_tf32(f1, Ahi[ot][1], Alo[ot][1]);
                    split_tf32(f2, Ahi[ot][2], Alo[ot][2]);
                    split_tf32(f3, Ahi[ot][3], Alo[ot][3]);
                }
#pragma unroll
                for (int nt = 0; nt < 4; ++nt) {
                    int mb = m_off + nt * 8;
                    float f0 = sH[(k0 + tg    ) * LDS_S + mb + gq];
                    float f1 = sH[(k0 + tg + 4) * LDS_S + mb + gq];
                    split_tf32(f0, Bhi[nt][0], Blo[nt][0]);
                    split_tf32(f1, Bhi[nt][1], Blo[nt][1]);
                }
#pragma unroll
                for (int ot = 0; ot < 2; ++ot)
#pragma unroll
                    for (int nt = 0; nt < 4; ++nt) {
                        mma_tf32(acc[ot][nt], Ahi[ot], Bhi[nt]);
                        mma_tf32(acc[ot][nt], Ahi[ot], Blo[nt]);
                        mma_tf32(acc[ot][nt], Alo[ot], Bhi[nt]);
                    }
            }

            // epilogue: exp-transform + scatter to g_U [(b*NN+m)*512 + o]
#pragma unroll
            for (int ot = 0; ot < 2; ++ot) {
                int orow = o0 + o_off + ot * 16 + gq;
#pragma unroll
                for (int nt = 0; nt < 4; ++nt) {
                    int mcol = m0 + m_off + nt * 8 + 2 * tg;
                    float* p0 = g_U + ((size_t)bA * NN + mcol) * 512 + orow;
                    p0[0]         = exp_xform(acc[ot][nt][0], gate3);
                    p0[512]       = exp_xform(acc[ot][nt][1], gate3);
                    p0[8]         = exp_xform(acc[ot][nt][2], gate3);
                    p0[512 + 8]   = exp_xform(acc[ot][nt][3], gate3);
                }
            }
        }

        batch_barrier(bA);

        // ---------------- Phase B: gate + max over K ----------------
        {
            const float* Vt    = Vbase + (size_t)t * VSLAB;
            const float* Cprev = t ? g_c[(t-1) & 1] : nullptr;
            float* Hout = Hs + (size_t)t * SBT;
            float* Cout = g_c[t & 1];
            int b = bA;

#pragma unroll
            for (int i = 0; i < 2; ++i) {            // 32 points/block, 2/warp
                int n = lb * 32 + warp * 2 + i;
                int mreg = 0;
                if (lane < KK)
                    mreg = g_idx[(((size_t)b*TT + t) * NN + n) * KK + lane];

                const float* Vp = Vt + ((size_t)b * NN + n) * 512 + lane * 4;
                float4 v0 = *reinterpret_cast<const float4*>(Vp);
                float4 v1 = *reinterpret_cast<const float4*>(Vp + 128);
                float4 v2 = *reinterpret_cast<const float4*>(Vp + 256);
                float4 v3 = *reinterpret_cast<const float4*>(Vp + 384);

                float4 hmax = make_float4(-1e30f,-1e30f,-1e30f,-1e30f);
                float4 cmax = hmax;
#pragma unroll 4
                for (int k = 0; k < KK; ++k) {
                    int m = __shfl_sync(0xffffffffu, mreg, k);
                    const float* Up = g_U + ((size_t)b * NN + m) * 512 + lane * 4;
                    float4 u0 = __ldcg(reinterpret_cast<const float4*>(Up));
                    float4 u1 = __ldcg(reinterpret_cast<const float4*>(Up + 128));
                    float4 u2 = __ldcg(reinterpret_cast<const float4*>(Up + 256));
                    float4 u3 = __ldcg(reinterpret_cast<const float4*>(Up + 384));
                    float4 cg = make_float4(0.f, 0.f, 0.f, 0.f);
                    if (Cprev)
                        cg = __ldcg(reinterpret_cast<const float4*>(
                                 Cprev + ((size_t)b * NN + m) * HD + lane * 4));
                    float cn, hn;
                    gate4e(v0.x*u0.x, v1.x*u1.x, v2.x*u2.x, v3.x*u3.x, cg.x, cn, hn);
                    cmax.x = fmaxf(cmax.x, cn); hmax.x = fmaxf(hmax.x, hn);
                    gate4e(v0.y*u0.y, v1.y*u1.y, v2.y*u2.y, v3.y*u3.y, cg.y, cn, hn);
                    cmax.y = fmaxf(cmax.y, cn); hmax.y = fmaxf(hmax.y, hn);
                    gate4e(v0.z*u0.z, v1.z*u1.z, v2.z*u2.z, v3.z*u3.z, cg.z, cn, hn);
                    cmax.z = fmaxf(cmax.z, cn); hmax.z = fmaxf(hmax.z, hn);
                    gate4e(v0.w*u0.w, v1.w*u1.w, v2.w*u2.w, v3.w*u3.w, cg.w, cn, hn);
                    cmax.w = fmaxf(cmax.w, cn); hmax.w = fmaxf(hmax.w, hn);
                }
                size_t o = ((size_t)b * NN + n) * HD + lane * 4;
                *reinterpret_cast<float4*>(Hout + o) = hmax;
                *reinterpret_cast<float4*>(Cout + o) = cmax;
            }
        }

        batch_barrier(bA);
    }
}

// ---------------- output assembly ----------------
__global__ void out1_pos_kernel(const float* __restrict__ x, float* __restrict__ out) {
    int i = blockIdx.x * 256 + threadIdx.x;
    if (i < BB*TT*4*NN) {
        int bt = i >> 12;
        int r  = i & 4095;
        out[(size_t)bt * 132 * NN + r] = x[i];
    }
}

__global__ void out1_hs_kernel(float* __restrict__ out) {
    __shared__ float tile[32][33];
    int n0 = blockIdx.x * 32, j0 = blockIdx.y * 32, bt = blockIdx.z;
    int b = bt >> 5, t = bt & 31;
    int tx = threadIdx.x, ty = threadIdx.y;
    tile[ty][tx] = g_hs1[(((size_t)t*BB + b) * NN + n0 + ty) * HD + j0 + tx];
    __syncthreads();
    out[((size_t)bt * 132 + 4 + j0 + ty) * NN + n0 + tx] = tile[tx][ty];
}

__global__ void hc_kernel(float* __restrict__ out) {
    __shared__ float th[32][33];
    __shared__ float tc[32][33];
    int n0 = blockIdx.x * 32, j0 = blockIdx.y * 32, b = blockIdx.z;
    int tx = threadIdx.x, ty = threadIdx.y;
    th[ty][tx] = g_hs1[(((size_t)(TT-1)*BB + b) * NN + n0 + ty) * HD + j0 + tx];
    tc[ty][tx] = g_c[(TT-1) & 1][((size_t)b * NN + n0 + ty) * HD + j0 + tx];
    __syncthreads();
    size_t dst = ((size_t)b * HD + j0 + ty) * NN + n0 + tx;
    out[OFF_H + dst] = th[tx][ty];
    out[OFF_C + dst] = tc[tx][ty];
}

__global__ void idxf_kernel(float* __restrict__ out) {
    int i = blockIdx.x * 256 + threadIdx.x;
    out[OFF_I + i] = (float)g_idx[i];
}

// ---------------- launch ----------------
extern "C" void kernel_launch(void* const* d_in, const int* in_sizes, int n_in,
                              void* d_out, int out_size) {
    const float* x  = (const float*)d_in[0];
    const float* w0 = (const float*)d_in[1];
    const float* b0 = (const float*)d_in[2];
    const float* w1 = (const float*)d_in[3];
    const float* b1 = (const float*)d_in[4];
    float* out = (float*)d_out;

    cudaFuncSetAttribute(layer_kernel,
                         cudaFuncAttributeMaxDynamicSharedMemorySize, DYN_SMEM);

    knn_kernel<<<dim3(4, TT, BB), 256>>>(x);
    wdiff_kernel<<<4, 128>>>(w0, w1);

    dim3 gv(8, 16, BB*TT);

    vgemm_kernel<<<gv, 256>>>(0, x, b0, w1, b1);          // V0, all t
    layer_kernel<<<LBLK, 512, DYN_SMEM>>>(0, x, w0, w1);  // layer 0 recurrence
    vgemm_kernel<<<gv, 256>>>(1, x, b0, w1, b1);          // V1, all t
    layer_kernel<<<LBLK, 512, DYN_SMEM>>>(1, x, w0, w1);  // layer 1 recurrence

    out1_pos_kernel<<<2048, 256>>>(x, out);
    out1_hs_kernel<<<dim3(32, 4, BB*TT), dim3(32, 32)>>>(out);
    hc_kernel<<<dim3(32, 4, BB), dim3(32, 32)>>>(out);
    idxf_kernel<<<8192, 256>>>(out);
}